// round 6
// baseline (speedup 1.0000x reference)
#include <cuda_runtime.h>

#define BQ 4
#define LQ 2048
#define DM 64
#define ED 128
#define NQ 32
#define DCV 16
#define DTR 4
#define RQ 68            // DTR + 2*N
#define EPSQ 1e-5f
#define LOG2EF 1.4426950408889634f

#define CH 128           // steps per staged chunk in k3
#define NCH 16           // chunks (CH*NCH = LQ)
#define K3EG 4           // e-channels per k3 block (1 per warp)

// ---------------- scratch (device globals; no allocation allowed) ----------------
__device__ float  g_h[BQ * LQ * DM];             // residual stream
__device__ float  g_xz[BQ * LQ * 2 * ED];        // in_proj output (b,l,2e)
__device__ float2 g_dx2[BQ * ED * LQ];           // {delta, delta*xc}  (b,e,l)
__device__ float2 g_gate2[BQ * ED * LQ];         // {silu(z), Dp*xc*silu(z)} (b,e,l)
__device__ float2 g_bc2[BQ * LQ * NQ];           // {B,C} (b,t,n)
__device__ float  g_yout[BQ * ED * LQ];          // gated scan output (b,e,l)

__device__ __forceinline__ float ex2(float x) {
    float r; asm("ex2.approx.ftz.f32 %0, %1;" : "=f"(r) : "f"(x)); return r;
}

// ================= K1: rmsnorm + in_proj =================
__global__ void __launch_bounds__(256) k1_rms_inproj(
    const float* __restrict__ hin,
    const float* __restrict__ inw,   // (256, 64)
    const float* __restrict__ inb,
    const float* __restrict__ nw)
{
    __shared__ float s_nrow[16][68];

    int b  = blockIdx.x >> 7;
    int l0 = (blockIdx.x & 127) << 4;
    int tid = threadIdx.x;
    int lane = tid & 31, wid = tid >> 5;

    #pragma unroll
    for (int il = 0; il < 2; ++il) {
        int l = wid * 2 + il;
        const float* hr = hin + ((size_t)(b * LQ + l0 + l)) * DM;
        float v0 = hr[lane], v1 = hr[lane + 32];
        float ss = v0 * v0 + v1 * v1;
        #pragma unroll
        for (int s = 16; s; s >>= 1) ss += __shfl_xor_sync(~0u, ss, s);
        float r = rsqrtf(ss * (1.0f / DM) + EPSQ);
        s_nrow[l][lane]      = v0 * r * nw[lane];
        s_nrow[l][lane + 32] = v1 * r * nw[lane + 32];
    }
    __syncthreads();

    int c = tid;
    float acc[16];
    #pragma unroll
    for (int l = 0; l < 16; ++l) acc[l] = 0.f;

    const float4* w4p = (const float4*)inw + c * 16;
    #pragma unroll 1
    for (int k4 = 0; k4 < 16; ++k4) {
        float4 w = __ldg(&w4p[k4]);
        #pragma unroll
        for (int l = 0; l < 16; ++l) {
            float4 s = *(const float4*)&s_nrow[l][k4 * 4];
            acc[l] += w.x * s.x + w.y * s.y + w.z * s.z + w.w * s.w;
        }
    }
    float bb = inb[c];
    float* xzp = g_xz + ((size_t)(b * LQ + l0)) * 256 + c;
    #pragma unroll
    for (int l = 0; l < 16; ++l) xzp[(size_t)l * 256] = acc[l] + bb;
}

// ================= K2: dwconv + silu + xproj + dtproj + softplus + packing =================
#define K2_SMEM_FLOATS 19264
#define K2_SMEM_BYTES  (K2_SMEM_FLOATS * 4)

__global__ void __launch_bounds__(256) k2_conv_xproj(
    const float* __restrict__ convw,
    const float* __restrict__ convb,
    const float* __restrict__ xprojw,
    const float* __restrict__ dtw,
    const float* __restrict__ dtb,
    const float* __restrict__ Dpw)
{
    extern __shared__ float sm[];
    float* s_xin   = sm;
    float* s_convw = sm + 47 * 128;
    float* s_xw    = sm;
    float* s_dbc   = sm + 68 * 128;
    float* s_xc    = sm + 10912;
    float* s_z     = sm + 15136;

    int b  = blockIdx.x >> 6;
    int l0 = (blockIdx.x & 63) << 5;
    int tid = threadIdx.x;

    for (int i = tid; i < 128 * 16; i += 256) s_convw[i] = convw[i];
    for (int i = tid; i < 47 * 128; i += 256) {
        int r = i >> 7, ch = i & 127;
        int l = l0 - 15 + r;
        s_xin[i] = (l >= 0) ? g_xz[((size_t)(b * LQ + l)) * 256 + ch] : 0.f;
    }
    for (int i = tid; i < 32 * 128; i += 256) {
        int l = i >> 7, ch = i & 127;
        s_z[l * 129 + ch] = g_xz[((size_t)(b * LQ + l0 + l)) * 256 + 128 + ch];
    }
    __syncthreads();

    for (int i = tid; i < 32 * 128; i += 256) {
        int l = i >> 7, ch = i & 127;
        float acc = convb[ch];
        #pragma unroll
        for (int j = 0; j < DCV; ++j)
            acc += s_convw[ch * DCV + j] * s_xin[(l + j) * 128 + ch];
        float sg = 1.f / (1.f + __expf(-acc));
        s_xc[l * 132 + ch] = acc * sg;
    }
    __syncthreads();

    for (int i = tid; i < 68 * 128; i += 256) s_xw[i] = xprojw[i];
    __syncthreads();

    {
        int l = tid & 31, rg = tid >> 5;
        if (rg * 9 < RQ) {
            float acc[9];
            #pragma unroll
            for (int r = 0; r < 9; ++r) acc[r] = 0.f;
            const float4* xc4 = (const float4*)(s_xc + l * 132);
            #pragma unroll 1
            for (int kc = 0; kc < 4; ++kc) {
                float4 xr[8];
                #pragma unroll
                for (int q = 0; q < 8; ++q) xr[q] = xc4[kc * 8 + q];
                #pragma unroll
                for (int rr = 0; rr < 9; ++rr) {
                    int r = rg * 9 + rr;
                    if (r < RQ) {
                        const float4* w4 = (const float4*)(s_xw + r * 128 + kc * 32);
                        float a = acc[rr];
                        #pragma unroll
                        for (int q = 0; q < 8; ++q) {
                            float4 w = w4[q];
                            a += w.x * xr[q].x + w.y * xr[q].y + w.z * xr[q].z + w.w * xr[q].w;
                        }
                        acc[rr] = a;
                    }
                }
            }
            #pragma unroll
            for (int rr = 0; rr < 9; ++rr) {
                int r = rg * 9 + rr;
                if (r < RQ) s_dbc[l * 69 + r] = acc[rr];
            }
        }
    }
    __syncthreads();

    for (int i = tid; i < 32 * 128; i += 256) {
        int e = i >> 5, l = i & 31;
        const float* dr = s_dbc + l * 69;
        float4 wv = __ldg((const float4*)(dtw + e * 4));
        float v = dr[0] * wv.x + dr[1] * wv.y + dr[2] * wv.z + dr[3] * wv.w + dtb[e];
        float delta = (v > 20.f) ? v : log1pf(__expf(v));
        float xcv = s_xc[l * 132 + e];
        float z  = s_z[l * 129 + e];
        float gz = z / (1.f + __expf(-z));
        size_t oidx = ((size_t)(b * ED + e)) * LQ + l0 + l;
        g_dx2[oidx]   = make_float2(delta, delta * xcv);
        g_gate2[oidx] = make_float2(gz, Dpw[e] * xcv * gz);
    }
    for (int i = tid; i < 32 * 32; i += 256) {
        int l = i >> 5, n = i & 31;
        const float* dr = s_dbc + l * 69;
        g_bc2[((size_t)(b * LQ + l0 + l)) * 32 + n] = make_float2(dr[DTR + n], dr[DTR + NQ + n]);
    }
}

// ================= K3: single-pass selective scan =================
// grid: b(4) x egroup(32) = 128 blocks; 128 threads = 4 warps; warp = one e, lane = n.
// Block loops over 16 chunks of 128 steps; B/C + dx double-buffered in smem.
// dyn smem: s_bc[2][CH*NQ] (64KB) + s_dx[2][K3EG][CH] (8KB) = 72KB
#define K3_SMEM_BYTES ((2 * CH * NQ + 2 * K3EG * CH) * 8)

__global__ void __launch_bounds__(128) k3_scan(const float* __restrict__ Alog)
{
    extern __shared__ float2 sm2[];
    float2* s_bc = sm2;                                    // [2][CH*NQ]
    float2 (*s_dx)[K3EG][CH] = (float2(*)[K3EG][CH])(sm2 + 2 * CH * NQ);

    int eg = blockIdx.x & 31;
    int b  = blockIdx.x >> 5;
    int tid = threadIdx.x, lane = tid & 31, w = tid >> 5;
    int e = eg * K3EG + w;

    float aA = -__expf(Alog[e * NQ + lane]) * LOG2EF;

    const float4* bsrc = (const float4*)(g_bc2 + (size_t)b * LQ * NQ);   // chunk = 2048 float4
    const float4* dsrc = (const float4*)(g_dx2 + ((size_t)(b * ED + eg * K3EG)) * LQ);
    // NOTE: the 4 e-rows of this block are contiguous (e-major): rows eg*4..eg*4+3,
    // each LQ float2 = 1024 float4. Stage per chunk: 4 rows x 64 float4.

    // ---- stage chunk 0 into buffer 0 ----
    {
        float2* d0 = s_bc;                       // buf 0
        const float4* src = bsrc;                // chunk 0
        for (int i = tid; i < CH * NQ / 2; i += 128)
            *(float4*)(d0 + 2 * i) = __ldg(src + i);
        float2* dd = &s_dx[0][0][0];
        for (int i = tid; i < K3EG * CH / 2; i += 128) {
            int row = i >> 6, col = i & 63;      // 64 float4 per row-chunk
            *(float4*)(dd + (size_t)row * CH + 2 * col) = __ldg(dsrc + (size_t)row * (LQ / 2) + col);
        }
    }

    const float2* gtp = g_gate2 + ((size_t)(b * ED + e)) * LQ;
    float* yp = g_yout + ((size_t)(b * ED + e)) * LQ;

    float h = 0.f;
    #pragma unroll 1
    for (int c = 0; c < NCH; ++c) {
        int buf = c & 1;
        __syncthreads();                          // staged buffer ready

        // issue stage of next chunk into alternate buffer
        if (c + 1 < NCH) {
            int nb = buf ^ 1;
            float2* d0 = s_bc + nb * (CH * NQ);
            const float4* src = bsrc + (size_t)(c + 1) * (CH * NQ / 2);
            for (int i = tid; i < CH * NQ / 2; i += 128)
                *(float4*)(d0 + 2 * i) = __ldg(src + i);
            float2* dd = &s_dx[nb][0][0];
            const float4* dsc = dsrc + (c + 1) * (CH / 2);
            for (int i = tid; i < K3EG * CH / 2; i += 128) {
                int row = i >> 6, col = i & 63;
                *(float4*)(dd + (size_t)row * CH + 2 * col) = __ldg(dsc + (size_t)row * (LQ / 2) + col);
            }
        }

        const float2* dxc = s_dx[buf][w];
        const float2* bcc = s_bc + buf * (CH * NQ);

        #pragma unroll 1
        for (int t0 = 0; t0 < CH; t0 += 32) {
            float v[32];
            #pragma unroll
            for (int j = 0; j < 32; ++j) {
                float2 m  = dxc[t0 + j];
                float2 wv = bcc[(t0 + j) * NQ + lane];
                float dA = ex2(m.x * aA);
                h = fmaf(dA, h, m.y * wv.x);
                v[j] = h * wv.y;
            }
            // butterfly-transpose multi-reduce: lane L ends with sum for step t0+L
            #pragma unroll
            for (int d = 16; d >= 1; d >>= 1) {
                #pragma unroll
                for (int j = 0; j < d; ++j) {
                    float send  = (lane & d) ? v[j] : v[j + d];
                    float other = __shfl_xor_sync(~0u, send, d);
                    float keep  = (lane & d) ? v[j + d] : v[j];
                    v[j] = keep + other;
                }
            }
            int t = c * CH + t0 + lane;
            float2 g = __ldg(gtp + t);
            yp[t] = fmaf(v[0], g.x, g.y);
        }
    }
}

// ================= K4: out_proj + residual =================
__global__ void __launch_bounds__(256) k4_outproj(
    const float* __restrict__ ow,   // (64, 128)
    const float* __restrict__ ob,
    const float* __restrict__ hin,
    float* __restrict__ hout)
{
    __shared__ float s_y[16 * 132];

    int b  = blockIdx.x >> 7;
    int l0 = (blockIdx.x & 127) << 4;
    int tid = threadIdx.x;

    for (int i = tid; i < 128 * 16; i += 256) {
        int e = i >> 4, lc = i & 15;
        s_y[lc * 132 + e] = g_yout[((size_t)(b * 128 + e)) * LQ + l0 + lc];
    }
    __syncthreads();

    int d = tid & 63, lg = tid >> 6;
    float a0 = 0.f, a1 = 0.f, a2 = 0.f, a3 = 0.f;

    const float4* wp = (const float4*)(ow + d * 128);
    const float4* y0 = (const float4*)(s_y + (lg * 4 + 0) * 132);
    const float4* y1 = (const float4*)(s_y + (lg * 4 + 1) * 132);
    const float4* y2 = (const float4*)(s_y + (lg * 4 + 2) * 132);
    const float4* y3 = (const float4*)(s_y + (lg * 4 + 3) * 132);

    #pragma unroll 8
    for (int k4 = 0; k4 < 32; ++k4) {
        float4 w = __ldg(&wp[k4]);
        float4 v0 = y0[k4], v1 = y1[k4], v2 = y2[k4], v3 = y3[k4];
        a0 += w.x * v0.x + w.y * v0.y + w.z * v0.z + w.w * v0.w;
        a1 += w.x * v1.x + w.y * v1.y + w.z * v1.z + w.w * v1.w;
        a2 += w.x * v2.x + w.y * v2.y + w.z * v2.z + w.w * v2.w;
        a3 += w.x * v3.x + w.y * v3.y + w.z * v3.z + w.w * v3.w;
    }

    float bias = ob[d];
    size_t rbase = ((size_t)(b * LQ + l0 + lg * 4)) * DM + d;
    hout[rbase + 0 * DM] = hin[rbase + 0 * DM] + bias + a0;
    hout[rbase + 1 * DM] = hin[rbase + 1 * DM] + bias + a1;
    hout[rbase + 2 * DM] = hin[rbase + 2 * DM] + bias + a2;
    hout[rbase + 3 * DM] = hin[rbase + 3 * DM] + bias + a3;
}

// ================= final classifier head =================
__global__ void __launch_bounds__(128) k_final(
    const float* __restrict__ fcw, const float* __restrict__ fcb, float* __restrict__ out)
{
    int b = threadIdx.x >> 5, lane = threadIdx.x & 31;
    float s = 0.f;
    #pragma unroll
    for (int j = 0; j < 4; ++j) {
        int e = lane + 32 * j;
        s += g_yout[((size_t)(b * 128 + e)) * LQ + (LQ - 1)] * fcw[e];
    }
    #pragma unroll
    for (int d = 16; d; d >>= 1) s += __shfl_xor_sync(~0u, s, d);
    if (lane == 0) out[b] = s + fcb[0];
}

// ================= launch =================
extern "C" void kernel_launch(void* const* d_in, const int* in_sizes, int n_in,
                              void* d_out, int out_size)
{
    const float* x        = (const float*)d_in[0];
    const float* in_w     = (const float*)d_in[1];
    const float* in_b     = (const float*)d_in[2];
    const float* conv_w   = (const float*)d_in[3];
    const float* conv_b   = (const float*)d_in[4];
    const float* xproj_w  = (const float*)d_in[5];
    const float* dtproj_w = (const float*)d_in[6];
    const float* dtproj_b = (const float*)d_in[7];
    const float* A_log    = (const float*)d_in[8];
    const float* Dp       = (const float*)d_in[9];
    const float* outp_w   = (const float*)d_in[10];
    const float* outp_b   = (const float*)d_in[11];
    const float* norm_w   = (const float*)d_in[12];
    const float* fc_w     = (const float*)d_in[13];
    const float* fc_b     = (const float*)d_in[14];
    float* out = (float*)d_out;

    (void)in_sizes; (void)n_in; (void)out_size;

    cudaFuncSetAttribute(k2_conv_xproj, cudaFuncAttributeMaxDynamicSharedMemorySize, K2_SMEM_BYTES);
    cudaFuncSetAttribute(k3_scan,       cudaFuncAttributeMaxDynamicSharedMemorySize, K3_SMEM_BYTES);

    float* gh = nullptr;
    cudaGetSymbolAddress((void**)&gh, g_h);

    for (int i = 0; i < 4; ++i) {
        const float* hin = (i == 0) ? x : gh;
        k1_rms_inproj<<<512, 256>>>(hin,
                                    in_w + (size_t)i * 2 * ED * DM,
                                    in_b + (size_t)i * 2 * ED,
                                    norm_w + (size_t)i * DM);
        k2_conv_xproj<<<256, 256, K2_SMEM_BYTES>>>(
            conv_w   + (size_t)i * ED * DCV,
            conv_b   + (size_t)i * ED,
            xproj_w  + (size_t)i * RQ * ED,
            dtproj_w + (size_t)i * ED * DTR,
            dtproj_b + (size_t)i * ED,
            Dp       + (size_t)i * ED);
        k3_scan<<<128, 128, K3_SMEM_BYTES>>>(A_log + (size_t)i * ED * NQ);
        if (i < 3)
            k4_outproj<<<512, 256>>>(
                outp_w + (size_t)i * DM * ED,
                outp_b + (size_t)i * DM,
                hin, gh);
    }
    k_final<<<1, 128>>>(fc_w, fc_b, out);
}

// round 7
// speedup vs baseline: 1.5680x; 1.5680x over previous
#include <cuda_runtime.h>

#define BQ 4
#define LQ 2048
#define DM 64
#define ED 128
#define NQ 32
#define DCV 16
#define DTR 4
#define RQ 68            // DTR + 2*N
#define EPSQ 1e-5f
#define LOG2EF 1.4426950408889634f

#define CH 128           // steps per chunk (k3)
#define NCH 16           // chunks
#define EG 16            // e-channels per scan block

// ---------------- scratch (device globals; no allocation allowed) ----------------
__device__ float  g_h[BQ * LQ * DM];             // residual stream
__device__ float  g_xz[BQ * LQ * 2 * ED];        // in_proj output (b,l,2e)
__device__ float2 g_dx2[BQ * ED * LQ];           // {delta, delta*xc}  (b,e,l)
__device__ float2 g_gate2[BQ * ED * LQ];         // {silu(z), Dp*xc*silu(z)} (b,e,l)
__device__ float  g_bB[BQ * LQ * NQ];            // B (b,t,n)
__device__ float2 g_bc2[BQ * LQ * NQ];           // {B,C} (b,t,n)
__device__ float  g_yout[BQ * ED * LQ];          // gated scan output (b,e,l)
__device__ float2 g_carry[BQ * ED * NCH * NQ];   // {h_final, P}

__device__ __forceinline__ float ex2(float x) {
    float r; asm("ex2.approx.ftz.f32 %0, %1;" : "=f"(r) : "f"(x)); return r;
}

// ================= K1: rmsnorm + in_proj =================
// grid: B * (L/32) = 256 blocks, 256 threads. 32 timesteps per block.
// Weights staged transposed in smem [k][c] (pad 257): staging conflict-free,
// GEMM weight reads coalesced LDS.32, activation reads LDS.128 broadcast.
#define K1_SMEM_FLOATS (64 * 257 + 32 * 68)
#define K1_SMEM_BYTES  (K1_SMEM_FLOATS * 4)

__global__ void __launch_bounds__(256) k1_rms_inproj(
    const float* __restrict__ hin,
    const float* __restrict__ inw,   // (256, 64)
    const float* __restrict__ inb,
    const float* __restrict__ nw)
{
    extern __shared__ float sm1[];
    float* s_w    = sm1;              // [k=64][c=256] pad 257
    float* s_nrow = sm1 + 64 * 257;   // [l=32][k=64] pad 68

    int b  = blockIdx.x >> 6;
    int l0 = (blockIdx.x & 63) << 5;
    int tid = threadIdx.x;
    int lane = tid & 31, wid = tid >> 5;

    // stage weights transposed: read coalesced, write stride-257 (conflict-free)
    for (int i = tid; i < 256 * 64; i += 256)
        s_w[(i & 63) * 257 + (i >> 6)] = inw[i];

    // rmsnorm: 8 warps x 4 rows
    #pragma unroll
    for (int il = 0; il < 4; ++il) {
        int l = wid * 4 + il;
        const float* hr = hin + ((size_t)(b * LQ + l0 + l)) * DM;
        float v0 = hr[lane], v1 = hr[lane + 32];
        float ss = v0 * v0 + v1 * v1;
        #pragma unroll
        for (int s = 16; s; s >>= 1) ss += __shfl_xor_sync(~0u, ss, s);
        float r = rsqrtf(ss * (1.0f / DM) + EPSQ);
        s_nrow[l * 68 + lane]      = v0 * r * nw[lane];
        s_nrow[l * 68 + lane + 32] = v1 * r * nw[lane + 32];
    }
    __syncthreads();

    // GEMM: thread = output channel c; acc over 32 l positions
    int c = tid;
    float acc[32];
    #pragma unroll
    for (int l = 0; l < 32; ++l) acc[l] = 0.f;

    #pragma unroll 1
    for (int k4 = 0; k4 < 16; ++k4) {
        float w0 = s_w[(k4 * 4 + 0) * 257 + c];
        float w1 = s_w[(k4 * 4 + 1) * 257 + c];
        float w2 = s_w[(k4 * 4 + 2) * 257 + c];
        float w3 = s_w[(k4 * 4 + 3) * 257 + c];
        #pragma unroll
        for (int l = 0; l < 32; ++l) {
            float4 x = *(const float4*)&s_nrow[l * 68 + k4 * 4];   // broadcast
            acc[l] += w0 * x.x + w1 * x.y + w2 * x.z + w3 * x.w;
        }
    }
    float bb = inb[c];
    float* xzp = g_xz + ((size_t)(b * LQ + l0)) * 256 + c;
    #pragma unroll
    for (int l = 0; l < 32; ++l) xzp[(size_t)l * 256] = acc[l] + bb;
}

// ================= K2: dwconv + silu + xproj + dtproj + softplus + packing =================
#define K2_SMEM_FLOATS 19264
#define K2_SMEM_BYTES  (K2_SMEM_FLOATS * 4)

__global__ void __launch_bounds__(256) k2_conv_xproj(
    const float* __restrict__ convw,
    const float* __restrict__ convb,
    const float* __restrict__ xprojw,
    const float* __restrict__ dtw,
    const float* __restrict__ dtb,
    const float* __restrict__ Dpw)
{
    extern __shared__ float sm[];
    float* s_xin   = sm;
    float* s_convw = sm + 47 * 128;
    float* s_xw    = sm;
    float* s_dbc   = sm + 68 * 128;
    float* s_xc    = sm + 10912;
    float* s_z     = sm + 15136;

    int b  = blockIdx.x >> 6;
    int l0 = (blockIdx.x & 63) << 5;
    int tid = threadIdx.x;

    for (int i = tid; i < 128 * 16; i += 256) s_convw[i] = convw[i];
    for (int i = tid; i < 47 * 128; i += 256) {
        int r = i >> 7, ch = i & 127;
        int l = l0 - 15 + r;
        s_xin[i] = (l >= 0) ? g_xz[((size_t)(b * LQ + l)) * 256 + ch] : 0.f;
    }
    for (int i = tid; i < 32 * 128; i += 256) {
        int l = i >> 7, ch = i & 127;
        s_z[l * 129 + ch] = g_xz[((size_t)(b * LQ + l0 + l)) * 256 + 128 + ch];
    }
    __syncthreads();

    for (int i = tid; i < 32 * 128; i += 256) {
        int l = i >> 7, ch = i & 127;
        float acc = convb[ch];
        #pragma unroll
        for (int j = 0; j < DCV; ++j)
            acc += s_convw[ch * DCV + j] * s_xin[(l + j) * 128 + ch];
        float sg = 1.f / (1.f + __expf(-acc));
        s_xc[l * 132 + ch] = acc * sg;
    }
    __syncthreads();

    for (int i = tid; i < 68 * 128; i += 256) s_xw[i] = xprojw[i];
    __syncthreads();

    {
        int l = tid & 31, rg = tid >> 5;
        if (rg * 9 < RQ) {
            float acc[9];
            #pragma unroll
            for (int r = 0; r < 9; ++r) acc[r] = 0.f;
            const float4* xc4 = (const float4*)(s_xc + l * 132);
            #pragma unroll 1
            for (int kc = 0; kc < 4; ++kc) {
                float4 xr[8];
                #pragma unroll
                for (int q = 0; q < 8; ++q) xr[q] = xc4[kc * 8 + q];
                #pragma unroll
                for (int rr = 0; rr < 9; ++rr) {
                    int r = rg * 9 + rr;
                    if (r < RQ) {
                        const float4* w4 = (const float4*)(s_xw + r * 128 + kc * 32);
                        float a = acc[rr];
                        #pragma unroll
                        for (int q = 0; q < 8; ++q) {
                            float4 w = w4[q];
                            a += w.x * xr[q].x + w.y * xr[q].y + w.z * xr[q].z + w.w * xr[q].w;
                        }
                        acc[rr] = a;
                    }
                }
            }
            #pragma unroll
            for (int rr = 0; rr < 9; ++rr) {
                int r = rg * 9 + rr;
                if (r < RQ) s_dbc[l * 69 + r] = acc[rr];
            }
        }
    }
    __syncthreads();

    for (int i = tid; i < 32 * 128; i += 256) {
        int e = i >> 5, l = i & 31;
        const float* dr = s_dbc + l * 69;
        float4 wv = __ldg((const float4*)(dtw + e * 4));
        float v = dr[0] * wv.x + dr[1] * wv.y + dr[2] * wv.z + dr[3] * wv.w + dtb[e];
        float delta = (v > 20.f) ? v : log1pf(__expf(v));
        float xcv = s_xc[l * 132 + e];
        float z  = s_z[l * 129 + e];
        float gz = z / (1.f + __expf(-z));
        size_t oidx = ((size_t)(b * ED + e)) * LQ + l0 + l;
        g_dx2[oidx]   = make_float2(delta, delta * xcv);
        g_gate2[oidx] = make_float2(gz, Dpw[e] * xcv * gz);
    }
    for (int i = tid; i < 32 * 32; i += 256) {
        int l = i >> 5, n = i & 31;
        const float* dr = s_dbc + l * 69;
        size_t oidx = ((size_t)(b * LQ + l0 + l)) * 32 + n;
        float Bv = dr[DTR + n], Cv = dr[DTR + NQ + n];
        g_bB[oidx]  = Bv;
        g_bc2[oidx] = make_float2(Bv, Cv);
    }
}

// ================= K3a: local chunk scan (carry out) =================
// grid: b(4) x chunk(16) x egroup(8) = 512 blocks; 512 threads = 16 warps = 16 e's.
__global__ void __launch_bounds__(512) k3a_scan_local(const float* __restrict__ Alog)
{
    __shared__ float  s_b[CH * NQ];        // 16 KB
    __shared__ float2 s_dx[EG][CH];        // 16 KB

    int eg = blockIdx.x & 7;
    int c  = (blockIdx.x >> 3) & 15;
    int b  = blockIdx.x >> 7;
    int tid = threadIdx.x, lane = tid & 31, w = tid >> 5;
    int e = eg * EG + w;

    const float* bsrc = g_bB + ((size_t)(b * LQ) + c * CH) * NQ;
    for (int i = tid; i < CH * NQ; i += 512) s_b[i] = bsrc[i];
    {
        const float2* dsrc = g_dx2 + ((size_t)(b * ED + e)) * LQ + c * CH;
        #pragma unroll
        for (int k = 0; k < CH / 32; ++k) s_dx[w][k * 32 + lane] = __ldg(dsrc + k * 32 + lane);
    }
    __syncthreads();

    float aA = -__expf(Alog[e * NQ + lane]) * LOG2EF;

    float h = 0.f, P = 1.f;
    #pragma unroll 8
    for (int j = 0; j < CH; ++j) {
        float2 m = s_dx[w][j];
        float dA = ex2(m.x * aA);
        h = fmaf(dA, h, m.y * s_b[j * NQ + lane]);
        P *= dA;
    }
    g_carry[(((size_t)(b * ED + e)) * NCH + c) * NQ + lane] = make_float2(h, P);
}

// ================= K3c: combine prologue + rescan + multi-reduce + gate =================
#define K3C_SMEM_BYTES ((CH * NQ + EG * CH) * 8)

__global__ void __launch_bounds__(512) k3c_scan_out(const float* __restrict__ Alog)
{
    extern __shared__ float2 sm2[];
    float2* s_bc = sm2;                 // [t][n]
    float2 (*s_dx)[CH] = (float2(*)[CH])(sm2 + CH * NQ);

    int eg = blockIdx.x & 7;
    int c  = (blockIdx.x >> 3) & 15;
    int b  = blockIdx.x >> 7;
    int tid = threadIdx.x, lane = tid & 31, w = tid >> 5;
    int e = eg * EG + w;

    {
        const float2* bsrc = g_bc2 + ((size_t)(b * LQ) + c * CH) * NQ;
        for (int i = tid; i < CH * NQ; i += 512) s_bc[i] = bsrc[i];
        const float2* dsrc = g_dx2 + ((size_t)(b * ED + e)) * LQ + c * CH;
        #pragma unroll
        for (int k = 0; k < CH / 32; ++k) s_dx[w][k * 32 + lane] = __ldg(dsrc + k * 32 + lane);
    }

    float h = 0.f;
    if (c > 0) {
        const float2* cp = g_carry + (((size_t)(b * ED + e)) * NCH) * NQ + lane;
        #pragma unroll 4
        for (int cc = 0; cc < c; ++cc) {
            float2 v = __ldg(cp + (size_t)cc * NQ);
            h = fmaf(v.y, h, v.x);
        }
    }
    __syncthreads();

    float aA = -__expf(Alog[e * NQ + lane]) * LOG2EF;
    const float2* gtp = g_gate2 + ((size_t)(b * ED + e)) * LQ + c * CH;
    float* yp = g_yout + ((size_t)(b * ED + e)) * LQ + c * CH;

    for (int t0 = 0; t0 < CH; t0 += 32) {
        float v[32];
        #pragma unroll
        for (int j = 0; j < 32; ++j) {
            float2 m = s_dx[w][t0 + j];
            float2 wv = s_bc[(t0 + j) * NQ + lane];
            float dA = ex2(m.x * aA);
            h = fmaf(dA, h, m.y * wv.x);
            v[j] = h * wv.y;
        }
        #pragma unroll
        for (int d = 16; d >= 1; d >>= 1) {
            #pragma unroll
            for (int j = 0; j < d; ++j) {
                float send  = (lane & d) ? v[j] : v[j + d];
                float other = __shfl_xor_sync(~0u, send, d);
                float keep  = (lane & d) ? v[j + d] : v[j];
                v[j] = keep + other;
            }
        }
        float2 g = __ldg(gtp + t0 + lane);
        yp[t0 + lane] = fmaf(v[0], g.x, g.y);
    }
}

// ================= K4: out_proj + residual =================
// grid: B * (L/32) = 256 blocks, 256 threads. Weights staged transposed [k][d] (pad 65),
// y staged [k][l] (pad 36). Thread = (d, l-group of 8). All LDS conflict-free/broadcast.
#define K4_SMEM_FLOATS (128 * 65 + 128 * 36)
#define K4_SMEM_BYTES  (K4_SMEM_FLOATS * 4)

__global__ void __launch_bounds__(256) k4_outproj(
    const float* __restrict__ ow,   // (64, 128)
    const float* __restrict__ ob,
    const float* __restrict__ hin,
    float* __restrict__ hout)
{
    extern __shared__ float sm4[];
    float* s_wT = sm4;               // [k=128][d=64] pad 65
    float* s_yT = sm4 + 128 * 65;    // [k=128][l=32] pad 36

    int b  = blockIdx.x >> 6;
    int l0 = (blockIdx.x & 63) << 5;
    int tid = threadIdx.x;

    // stage weights transposed: read coalesced, write stride-65 conflict-free
    for (int i = tid; i < 64 * 128; i += 256)
        s_wT[(i & 127) * 65 + (i >> 7)] = ow[i];
    // stage y: [e][l] rows, 128B coalesced reads, conflict-free writes
    for (int i = tid; i < 128 * 32; i += 256) {
        int e = i >> 5, l = i & 31;
        s_yT[e * 36 + l] = g_yout[((size_t)(b * 128 + e)) * LQ + l0 + l];
    }
    __syncthreads();

    int d = tid & 63, lg = tid >> 6;   // 4 groups x 8 l
    float acc[8];
    #pragma unroll
    for (int j = 0; j < 8; ++j) acc[j] = 0.f;

    #pragma unroll 4
    for (int k = 0; k < 128; ++k) {
        float w = s_wT[k * 65 + d];                         // coalesced LDS.32
        float4 x0 = *(const float4*)&s_yT[k * 36 + lg * 8];     // broadcast
        float4 x1 = *(const float4*)&s_yT[k * 36 + lg * 8 + 4]; // broadcast
        acc[0] += w * x0.x; acc[1] += w * x0.y; acc[2] += w * x0.z; acc[3] += w * x0.w;
        acc[4] += w * x1.x; acc[5] += w * x1.y; acc[6] += w * x1.z; acc[7] += w * x1.w;
    }

    float bias = ob[d];
    #pragma unroll
    for (int j = 0; j < 8; ++j) {
        int l = lg * 8 + j;
        size_t idx = ((size_t)(b * LQ + l0 + l)) * DM + d;
        hout[idx] = hin[idx] + bias + acc[j];
    }
}

// ================= final classifier head =================
__global__ void __launch_bounds__(128) k_final(
    const float* __restrict__ fcw, const float* __restrict__ fcb, float* __restrict__ out)
{
    int b = threadIdx.x >> 5, lane = threadIdx.x & 31;
    float s = 0.f;
    #pragma unroll
    for (int j = 0; j < 4; ++j) {
        int e = lane + 32 * j;
        s += g_yout[((size_t)(b * 128 + e)) * LQ + (LQ - 1)] * fcw[e];
    }
    #pragma unroll
    for (int d = 16; d; d >>= 1) s += __shfl_xor_sync(~0u, s, d);
    if (lane == 0) out[b] = s + fcb[0];
}

// ================= launch =================
extern "C" void kernel_launch(void* const* d_in, const int* in_sizes, int n_in,
                              void* d_out, int out_size)
{
    const float* x        = (const float*)d_in[0];
    const float* in_w     = (const float*)d_in[1];
    const float* in_b     = (const float*)d_in[2];
    const float* conv_w   = (const float*)d_in[3];
    const float* conv_b   = (const float*)d_in[4];
    const float* xproj_w  = (const float*)d_in[5];
    const float* dtproj_w = (const float*)d_in[6];
    const float* dtproj_b = (const float*)d_in[7];
    const float* A_log    = (const float*)d_in[8];
    const float* Dp       = (const float*)d_in[9];
    const float* outp_w   = (const float*)d_in[10];
    const float* outp_b   = (const float*)d_in[11];
    const float* norm_w   = (const float*)d_in[12];
    const float* fc_w     = (const float*)d_in[13];
    const float* fc_b     = (const float*)d_in[14];
    float* out = (float*)d_out;

    (void)in_sizes; (void)n_in; (void)out_size;

    cudaFuncSetAttribute(k1_rms_inproj, cudaFuncAttributeMaxDynamicSharedMemorySize, K1_SMEM_BYTES);
    cudaFuncSetAttribute(k2_conv_xproj, cudaFuncAttributeMaxDynamicSharedMemorySize, K2_SMEM_BYTES);
    cudaFuncSetAttribute(k3c_scan_out,  cudaFuncAttributeMaxDynamicSharedMemorySize, K3C_SMEM_BYTES);
    cudaFuncSetAttribute(k4_outproj,    cudaFuncAttributeMaxDynamicSharedMemorySize, K4_SMEM_BYTES);

    float* gh = nullptr;
    cudaGetSymbolAddress((void**)&gh, g_h);

    for (int i = 0; i < 4; ++i) {
        const float* hin = (i == 0) ? x : gh;
        k1_rms_inproj<<<256, 256, K1_SMEM_BYTES>>>(hin,
                                    in_w + (size_t)i * 2 * ED * DM,
                                    in_b + (size_t)i * 2 * ED,
                                    norm_w + (size_t)i * DM);
        k2_conv_xproj<<<256, 256, K2_SMEM_BYTES>>>(
            conv_w   + (size_t)i * ED * DCV,
            conv_b   + (size_t)i * ED,
            xproj_w  + (size_t)i * RQ * ED,
            dtproj_w + (size_t)i * ED * DTR,
            dtproj_b + (size_t)i * ED,
            Dp       + (size_t)i * ED);
        const float* Al = A_log + (size_t)i * ED * NQ;
        k3a_scan_local<<<512, 512>>>(Al);
        k3c_scan_out<<<512, 512, K3C_SMEM_BYTES>>>(Al);
        if (i < 3)
            k4_outproj<<<256, 256, K4_SMEM_BYTES>>>(
                outp_w + (size_t)i * DM * ED,
                outp_b + (size_t)i * DM,
                hin, gh);
    }
    k_final<<<1, 128>>>(fc_w, fc_b, out);
}

// round 8
// speedup vs baseline: 1.6126x; 1.0284x over previous
#include <cuda_runtime.h>

#define BQ 4
#define LQ 2048
#define DM 64
#define ED 128
#define NQ 32
#define DCV 16
#define DTR 4
#define RQ 68            // DTR + 2*N
#define EPSQ 1e-5f
#define LOG2EF 1.4426950408889634f

#define CH 256           // steps per chunk (k3)
#define NCH 8            // chunks
#define EG 16            // e-channels per scan block

// ---------------- scratch (device globals; no allocation allowed) ----------------
__device__ float  g_h[BQ * LQ * DM];             // residual stream
__device__ float  g_xz[BQ * LQ * 2 * ED];        // in_proj output (b,l,2e)
__device__ float2 g_dx2[BQ * ED * LQ];           // {delta, delta*xc}  (b,e,l)
__device__ float2 g_gate2[BQ * ED * LQ];         // {silu(z), Dp*xc*silu(z)} (b,e,l)
__device__ float  g_bBT[BQ * NCH * NQ * CH];     // B, (b,chunk,n,t)
__device__ float2 g_bcT[BQ * NCH * NQ * CH];     // {B,C}, (b,chunk,n,t)
__device__ float  g_yout[BQ * ED * LQ];          // gated scan output (b,e,l)
__device__ float2 g_carry[BQ * ED * NCH * NQ];   // {h_final, P}

__device__ __forceinline__ float ex2(float x) {
    float r; asm("ex2.approx.ftz.f32 %0, %1;" : "=f"(r) : "f"(x)); return r;
}

// ================= K1: rmsnorm + in_proj =================
#define K1_SMEM_FLOATS (64 * 257 + 32 * 68)
#define K1_SMEM_BYTES  (K1_SMEM_FLOATS * 4)

__global__ void __launch_bounds__(256) k1_rms_inproj(
    const float* __restrict__ hin,
    const float* __restrict__ inw,   // (256, 64)
    const float* __restrict__ inb,
    const float* __restrict__ nw)
{
    extern __shared__ float sm1[];
    float* s_w    = sm1;              // [k=64][c=256] pad 257
    float* s_nrow = sm1 + 64 * 257;   // [l=32][k=64] pad 68

    int b  = blockIdx.x >> 6;
    int l0 = (blockIdx.x & 63) << 5;
    int tid = threadIdx.x;
    int lane = tid & 31, wid = tid >> 5;

    for (int i = tid; i < 256 * 64; i += 256)
        s_w[(i & 63) * 257 + (i >> 6)] = inw[i];

    #pragma unroll
    for (int il = 0; il < 4; ++il) {
        int l = wid * 4 + il;
        const float* hr = hin + ((size_t)(b * LQ + l0 + l)) * DM;
        float v0 = hr[lane], v1 = hr[lane + 32];
        float ss = v0 * v0 + v1 * v1;
        #pragma unroll
        for (int s = 16; s; s >>= 1) ss += __shfl_xor_sync(~0u, ss, s);
        float r = rsqrtf(ss * (1.0f / DM) + EPSQ);
        s_nrow[l * 68 + lane]      = v0 * r * nw[lane];
        s_nrow[l * 68 + lane + 32] = v1 * r * nw[lane + 32];
    }
    __syncthreads();

    int c = tid;
    float acc[32];
    #pragma unroll
    for (int l = 0; l < 32; ++l) acc[l] = 0.f;

    #pragma unroll 1
    for (int k4 = 0; k4 < 16; ++k4) {
        float w0 = s_w[(k4 * 4 + 0) * 257 + c];
        float w1 = s_w[(k4 * 4 + 1) * 257 + c];
        float w2 = s_w[(k4 * 4 + 2) * 257 + c];
        float w3 = s_w[(k4 * 4 + 3) * 257 + c];
        #pragma unroll
        for (int l = 0; l < 32; ++l) {
            float4 x = *(const float4*)&s_nrow[l * 68 + k4 * 4];
            acc[l] += w0 * x.x + w1 * x.y + w2 * x.z + w3 * x.w;
        }
    }
    float bb = inb[c];
    float* xzp = g_xz + ((size_t)(b * LQ + l0)) * 256 + c;
    #pragma unroll
    for (int l = 0; l < 32; ++l) xzp[(size_t)l * 256] = acc[l] + bb;
}

// ================= K2: dwconv + silu + xproj + dtproj + softplus + packing =================
#define K2_SMEM_FLOATS 19264
#define K2_SMEM_BYTES  (K2_SMEM_FLOATS * 4)

__global__ void __launch_bounds__(256) k2_conv_xproj(
    const float* __restrict__ convw,
    const float* __restrict__ convb,
    const float* __restrict__ xprojw,
    const float* __restrict__ dtw,
    const float* __restrict__ dtb,
    const float* __restrict__ Dpw)
{
    extern __shared__ float sm[];
    float* s_xin   = sm;
    float* s_convw = sm + 47 * 128;
    float* s_xw    = sm;
    float* s_dbc   = sm + 68 * 128;
    float* s_xc    = sm + 10912;
    float* s_z     = sm + 15136;

    int b  = blockIdx.x >> 6;
    int l0 = (blockIdx.x & 63) << 5;
    int tid = threadIdx.x;

    for (int i = tid; i < 128 * 16; i += 256) s_convw[i] = convw[i];
    for (int i = tid; i < 47 * 128; i += 256) {
        int r = i >> 7, ch = i & 127;
        int l = l0 - 15 + r;
        s_xin[i] = (l >= 0) ? g_xz[((size_t)(b * LQ + l)) * 256 + ch] : 0.f;
    }
    for (int i = tid; i < 32 * 128; i += 256) {
        int l = i >> 7, ch = i & 127;
        s_z[l * 129 + ch] = g_xz[((size_t)(b * LQ + l0 + l)) * 256 + 128 + ch];
    }
    __syncthreads();

    for (int i = tid; i < 32 * 128; i += 256) {
        int l = i >> 7, ch = i & 127;
        float acc = convb[ch];
        #pragma unroll
        for (int j = 0; j < DCV; ++j)
            acc += s_convw[ch * DCV + j] * s_xin[(l + j) * 128 + ch];
        float sg = 1.f / (1.f + __expf(-acc));
        s_xc[l * 132 + ch] = acc * sg;
    }
    __syncthreads();

    for (int i = tid; i < 68 * 128; i += 256) s_xw[i] = xprojw[i];
    __syncthreads();

    {
        int l = tid & 31, rg = tid >> 5;
        if (rg * 9 < RQ) {
            float acc[9];
            #pragma unroll
            for (int r = 0; r < 9; ++r) acc[r] = 0.f;
            const float4* xc4 = (const float4*)(s_xc + l * 132);
            #pragma unroll 1
            for (int kc = 0; kc < 4; ++kc) {
                float4 xr[8];
                #pragma unroll
                for (int q = 0; q < 8; ++q) xr[q] = xc4[kc * 8 + q];
                #pragma unroll
                for (int rr = 0; rr < 9; ++rr) {
                    int r = rg * 9 + rr;
                    if (r < RQ) {
                        const float4* w4 = (const float4*)(s_xw + r * 128 + kc * 32);
                        float a = acc[rr];
                        #pragma unroll
                        for (int q = 0; q < 8; ++q) {
                            float4 w = w4[q];
                            a += w.x * xr[q].x + w.y * xr[q].y + w.z * xr[q].z + w.w * xr[q].w;
                        }
                        acc[rr] = a;
                    }
                }
            }
            #pragma unroll
            for (int rr = 0; rr < 9; ++rr) {
                int r = rg * 9 + rr;
                if (r < RQ) s_dbc[l * 69 + r] = acc[rr];
            }
        }
    }
    __syncthreads();

    for (int i = tid; i < 32 * 128; i += 256) {
        int e = i >> 5, l = i & 31;
        const float* dr = s_dbc + l * 69;
        float4 wv = __ldg((const float4*)(dtw + e * 4));
        float v = dr[0] * wv.x + dr[1] * wv.y + dr[2] * wv.z + dr[3] * wv.w + dtb[e];
        float delta = (v > 20.f) ? v : log1pf(__expf(v));
        float xcv = s_xc[l * 132 + e];
        float z  = s_z[l * 129 + e];
        float gz = z / (1.f + __expf(-z));
        size_t oidx = ((size_t)(b * ED + e)) * LQ + l0 + l;
        g_dx2[oidx]   = make_float2(delta, delta * xcv);
        g_gate2[oidx] = make_float2(gz, Dpw[e] * xcv * gz);
    }
    // pack B, C transposed per chunk: (b, chunk, n, t) — l-fastest so writes coalesce
    {
        int chunk = l0 >> 8;       // CH = 256
        int tin   = l0 & (CH - 1);
        for (int i = tid; i < 32 * 32; i += 256) {
            int n = i >> 5, l = i & 31;
            const float* dr = s_dbc + l * 69;
            float Bv = dr[DTR + n], Cv = dr[DTR + NQ + n];
            size_t base = (((size_t)(b * NCH + chunk)) * NQ + n) * CH + tin + l;
            g_bBT[base] = Bv;
            g_bcT[base] = make_float2(Bv, Cv);
        }
    }
}

// ================= K3a: local chunk scan (carry out) =================
// grid: eg(8) x chunk(8) x b(4) = 256 blocks; 512 threads = 16 warps = 16 e's.
// dyn smem: s_b[NQ][CH+4] floats (33.3KB) + s_dx[EG][CH] float2 (32KB)
#define K3A_SMEM_BYTES (NQ * (CH + 4) * 4 + EG * CH * 8)

__global__ void __launch_bounds__(512) k3a_scan_local(const float* __restrict__ Alog)
{
    extern __shared__ float sma[];
    float* s_b = sma;                                   // [n][t] pad CH+4
    float2 (*s_dx)[CH] = (float2(*)[CH])(sma + NQ * (CH + 4));

    int eg = blockIdx.x & 7;
    int c  = (blockIdx.x >> 3) & 7;
    int b  = blockIdx.x >> 6;
    int tid = threadIdx.x, lane = tid & 31, w = tid >> 5;
    int e = eg * EG + w;

    // stage B (transposed layout, contiguous chunk): float4 both sides
    {
        const float4* src = (const float4*)(g_bBT + (((size_t)(b * NCH + c)) * NQ) * CH);
        for (int i = tid; i < NQ * CH / 4; i += 512) {
            int n = i >> 6, t4 = i & 63;               // 64 float4 per n-row
            *(float4*)(s_b + n * (CH + 4) + t4 * 4) = __ldg(src + i);
        }
        const float4* dsrc = (const float4*)(g_dx2 + ((size_t)(b * ED + e)) * LQ + c * CH);
        #pragma unroll
        for (int k = 0; k < CH / 64; ++k)
            *(float4*)(&s_dx[w][(k * 32 + lane) * 2]) = __ldg(dsrc + k * 32 + lane);
    }
    __syncthreads();

    float aA = -__expf(Alog[e * NQ + lane]) * LOG2EF;
    const float* bp = s_b + lane * (CH + 4);

    float h = 0.f, P = 1.f;
    #pragma unroll 4
    for (int j = 0; j < CH; j += 4) {
        float4 b4 = *(const float4*)(bp + j);          // 4 steps of B (this lane)
        float4 d0 = *(const float4*)(&s_dx[w][j]);     // steps j, j+1 (broadcast)
        float4 d1 = *(const float4*)(&s_dx[w][j + 2]); // steps j+2, j+3
        float dA;
        dA = ex2(d0.x * aA); h = fmaf(dA, h, d0.y * b4.x); P *= dA;
        dA = ex2(d0.z * aA); h = fmaf(dA, h, d0.w * b4.y); P *= dA;
        dA = ex2(d1.x * aA); h = fmaf(dA, h, d1.y * b4.z); P *= dA;
        dA = ex2(d1.z * aA); h = fmaf(dA, h, d1.w * b4.w); P *= dA;
    }
    g_carry[(((size_t)(b * ED + e)) * NCH + c) * NQ + lane] = make_float2(h, P);
}

// ================= K3c: combine prologue + rescan + multi-reduce + gate =================
// dyn smem: s_bc[NQ][CH+2] float2 (66KB) + s_dx[EG][CH] float2 (32KB)
#define K3C_SMEM_BYTES (NQ * (CH + 2) * 8 + EG * CH * 8)

__global__ void __launch_bounds__(512) k3c_scan_out(const float* __restrict__ Alog)
{
    extern __shared__ float2 sm2[];
    float2* s_bc = sm2;                                 // [n][t] pad CH+2
    float2 (*s_dx)[CH] = (float2(*)[CH])(sm2 + NQ * (CH + 2));

    int eg = blockIdx.x & 7;
    int c  = (blockIdx.x >> 3) & 7;
    int b  = blockIdx.x >> 6;
    int tid = threadIdx.x, lane = tid & 31, w = tid >> 5;
    int e = eg * EG + w;

    {
        const float4* src = (const float4*)(g_bcT + (((size_t)(b * NCH + c)) * NQ) * CH);
        float4* dstbase = (float4*)s_bc;
        for (int i = tid; i < NQ * CH / 2; i += 512) {
            int n = i >> 7, c4 = i & 127;              // 128 float4 per n-row
            dstbase[n * ((CH + 2) / 2) + c4] = __ldg(src + i);
        }
        const float4* dsrc = (const float4*)(g_dx2 + ((size_t)(b * ED + e)) * LQ + c * CH);
        #pragma unroll
        for (int k = 0; k < CH / 64; ++k)
            *(float4*)(&s_dx[w][(k * 32 + lane) * 2]) = __ldg(dsrc + k * 32 + lane);
    }

    // prologue: exclusive combine of carries for chunks < c
    float h = 0.f;
    if (c > 0) {
        const float2* cp = g_carry + (((size_t)(b * ED + e)) * NCH) * NQ + lane;
        #pragma unroll
        for (int cc = 0; cc < NCH - 1; ++cc) {
            if (cc >= c) break;
            float2 v = __ldg(cp + (size_t)cc * NQ);
            h = fmaf(v.y, h, v.x);
        }
    }
    __syncthreads();

    float aA = -__expf(Alog[e * NQ + lane]) * LOG2EF;
    const float2* gtp = g_gate2 + ((size_t)(b * ED + e)) * LQ + c * CH;
    float* yp = g_yout + ((size_t)(b * ED + e)) * LQ + c * CH;
    const float2* bcl = s_bc + lane * (CH + 2);

    #pragma unroll 1
    for (int t0 = 0; t0 < CH; t0 += 32) {
        float v[32];
        #pragma unroll
        for (int j = 0; j < 32; j += 2) {
            float4 bc = *(const float4*)(bcl + t0 + j);       // {B,C} steps j, j+1
            float4 dd = *(const float4*)(&s_dx[w][t0 + j]);   // dx steps j, j+1 (broadcast)
            float dA0 = ex2(dd.x * aA);
            h = fmaf(dA0, h, dd.y * bc.x);
            v[j] = h * bc.y;
            float dA1 = ex2(dd.z * aA);
            h = fmaf(dA1, h, dd.w * bc.z);
            v[j + 1] = h * bc.w;
        }
        // butterfly-transpose multi-reduce: lane L ends with sum for step t0+L
        #pragma unroll
        for (int d = 16; d >= 1; d >>= 1) {
            #pragma unroll
            for (int j = 0; j < d; ++j) {
                float send  = (lane & d) ? v[j] : v[j + d];
                float other = __shfl_xor_sync(~0u, send, d);
                float keep  = (lane & d) ? v[j + d] : v[j];
                v[j] = keep + other;
            }
        }
        float2 g = __ldg(gtp + t0 + lane);
        yp[t0 + lane] = fmaf(v[0], g.x, g.y);
    }
}

// ================= K4: out_proj + residual =================
#define K4_SMEM_FLOATS (128 * 65 + 128 * 36)
#define K4_SMEM_BYTES  (K4_SMEM_FLOATS * 4)

__global__ void __launch_bounds__(256) k4_outproj(
    const float* __restrict__ ow,   // (64, 128)
    const float* __restrict__ ob,
    const float* __restrict__ hin,
    float* __restrict__ hout)
{
    extern __shared__ float sm4[];
    float* s_wT = sm4;               // [k=128][d=64] pad 65
    float* s_yT = sm4 + 128 * 65;    // [k=128][l=32] pad 36

    int b  = blockIdx.x >> 6;
    int l0 = (blockIdx.x & 63) << 5;
    int tid = threadIdx.x;

    for (int i = tid; i < 64 * 128; i += 256)
        s_wT[(i & 127) * 65 + (i >> 7)] = ow[i];
    for (int i = tid; i < 128 * 32; i += 256) {
        int e = i >> 5, l = i & 31;
        s_yT[e * 36 + l] = g_yout[((size_t)(b * 128 + e)) * LQ + l0 + l];
    }
    __syncthreads();

    int d = tid & 63, lg = tid >> 6;
    float acc[8];
    #pragma unroll
    for (int j = 0; j < 8; ++j) acc[j] = 0.f;

    #pragma unroll 4
    for (int k = 0; k < 128; ++k) {
        float w = s_wT[k * 65 + d];
        float4 x0 = *(const float4*)&s_yT[k * 36 + lg * 8];
        float4 x1 = *(const float4*)&s_yT[k * 36 + lg * 8 + 4];
        acc[0] += w * x0.x; acc[1] += w * x0.y; acc[2] += w * x0.z; acc[3] += w * x0.w;
        acc[4] += w * x1.x; acc[5] += w * x1.y; acc[6] += w * x1.z; acc[7] += w * x1.w;
    }

    float bias = ob[d];
    #pragma unroll
    for (int j = 0; j < 8; ++j) {
        int l = lg * 8 + j;
        size_t idx = ((size_t)(b * LQ + l0 + l)) * DM + d;
        hout[idx] = hin[idx] + bias + acc[j];
    }
}

// ================= final classifier head =================
__global__ void __launch_bounds__(128) k_final(
    const float* __restrict__ fcw, const float* __restrict__ fcb, float* __restrict__ out)
{
    int b = threadIdx.x >> 5, lane = threadIdx.x & 31;
    float s = 0.f;
    #pragma unroll
    for (int j = 0; j < 4; ++j) {
        int e = lane + 32 * j;
        s += g_yout[((size_t)(b * 128 + e)) * LQ + (LQ - 1)] * fcw[e];
    }
    #pragma unroll
    for (int d = 16; d; d >>= 1) s += __shfl_xor_sync(~0u, s, d);
    if (lane == 0) out[b] = s + fcb[0];
}

// ================= launch =================
extern "C" void kernel_launch(void* const* d_in, const int* in_sizes, int n_in,
                              void* d_out, int out_size)
{
    const float* x        = (const float*)d_in[0];
    const float* in_w     = (const float*)d_in[1];
    const float* in_b     = (const float*)d_in[2];
    const float* conv_w   = (const float*)d_in[3];
    const float* conv_b   = (const float*)d_in[4];
    const float* xproj_w  = (const float*)d_in[5];
    const float* dtproj_w = (const float*)d_in[6];
    const float* dtproj_b = (const float*)d_in[7];
    const float* A_log    = (const float*)d_in[8];
    const float* Dp       = (const float*)d_in[9];
    const float* outp_w   = (const float*)d_in[10];
    const float* outp_b   = (const float*)d_in[11];
    const float* norm_w   = (const float*)d_in[12];
    const float* fc_w     = (const float*)d_in[13];
    const float* fc_b     = (const float*)d_in[14];
    float* out = (float*)d_out;

    (void)in_sizes; (void)n_in; (void)out_size;

    cudaFuncSetAttribute(k1_rms_inproj,  cudaFuncAttributeMaxDynamicSharedMemorySize, K1_SMEM_BYTES);
    cudaFuncSetAttribute(k2_conv_xproj,  cudaFuncAttributeMaxDynamicSharedMemorySize, K2_SMEM_BYTES);
    cudaFuncSetAttribute(k3a_scan_local, cudaFuncAttributeMaxDynamicSharedMemorySize, K3A_SMEM_BYTES);
    cudaFuncSetAttribute(k3c_scan_out,   cudaFuncAttributeMaxDynamicSharedMemorySize, K3C_SMEM_BYTES);
    cudaFuncSetAttribute(k4_outproj,     cudaFuncAttributeMaxDynamicSharedMemorySize, K4_SMEM_BYTES);

    float* gh = nullptr;
    cudaGetSymbolAddress((void**)&gh, g_h);

    for (int i = 0; i < 4; ++i) {
        const float* hin = (i == 0) ? x : gh;
        k1_rms_inproj<<<256, 256, K1_SMEM_BYTES>>>(hin,
                                    in_w + (size_t)i * 2 * ED * DM,
                                    in_b + (size_t)i * 2 * ED,
                                    norm_w + (size_t)i * DM);
        k2_conv_xproj<<<256, 256, K2_SMEM_BYTES>>>(
            conv_w   + (size_t)i * ED * DCV,
            conv_b   + (size_t)i * ED,
            xproj_w  + (size_t)i * RQ * ED,
            dtproj_w + (size_t)i * ED * DTR,
            dtproj_b + (size_t)i * ED,
            Dp       + (size_t)i * ED);
        const float* Al = A_log + (size_t)i * ED * NQ;
        k3a_scan_local<<<256, 512, K3A_SMEM_BYTES>>>(Al);
        k3c_scan_out<<<256, 512, K3C_SMEM_BYTES>>>(Al);
        if (i < 3)
            k4_outproj<<<256, 256, K4_SMEM_BYTES>>>(
                outp_w + (size_t)i * DM * ED,
                outp_b + (size_t)i * DM,
                hin, gh);
    }
    k_final<<<1, 128>>>(fc_w, fc_b, out);
}

// round 9
// speedup vs baseline: 1.6994x; 1.0538x over previous
#include <cuda_runtime.h>
#include <cuda_bf16.h>

#define BQ 4
#define LQ 2048
#define DM 64
#define ED 128
#define NQ 32
#define DCV 16
#define DTR 4
#define RQ 68            // DTR + 2*N
#define EPSQ 1e-5f
#define LOG2EF 1.4426950408889634f

#define CH 256           // steps per chunk (k3)
#define NCH 8            // chunks
#define EG 16            // e-channels per scan block

// ---------------- scratch (device globals; no allocation allowed) ----------------
__device__ float  g_h[BQ * LQ * DM];               // residual stream
__device__ float  g_xz[BQ * LQ * 2 * ED];          // in_proj output (b,l,2e)
__device__ float2 g_dx2[BQ * ED * LQ];             // {delta, delta*xc}  (b,e,l)
__device__ float2 g_gate2[BQ * ED * LQ];           // {silu(z), Dp*xc*silu(z)} (b,e,l)
__device__ __nv_bfloat16 g_bBT[BQ * NCH * NQ * CH];// B bf16, (b,chunk,n,t)
__device__ unsigned g_bcTp[BQ * NCH * NQ * CH];    // {B lo, C hi} bf16x2, (b,chunk,n,t)
__device__ float  g_yout[BQ * ED * LQ];            // RAW scan output (b,e,l) (gate applied downstream)
__device__ float2 g_carry[BQ * ED * NCH * NQ];     // {h_final, P}

__device__ __forceinline__ float ex2(float x) {
    float r; asm("ex2.approx.ftz.f32 %0, %1;" : "=f"(r) : "f"(x)); return r;
}

// ================= K1: rmsnorm + in_proj =================
#define K1_SMEM_FLOATS (64 * 257 + 32 * 68)
#define K1_SMEM_BYTES  (K1_SMEM_FLOATS * 4)

__global__ void __launch_bounds__(256) k1_rms_inproj(
    const float* __restrict__ hin,
    const float* __restrict__ inw,   // (256, 64)
    const float* __restrict__ inb,
    const float* __restrict__ nw)
{
    extern __shared__ float sm1[];
    float* s_w    = sm1;              // [k=64][c=256] pad 257
    float* s_nrow = sm1 + 64 * 257;   // [l=32][k=64] pad 68

    int b  = blockIdx.x >> 6;
    int l0 = (blockIdx.x & 63) << 5;
    int tid = threadIdx.x;
    int lane = tid & 31, wid = tid >> 5;

    for (int i = tid; i < 256 * 64; i += 256)
        s_w[(i & 63) * 257 + (i >> 6)] = inw[i];

    #pragma unroll
    for (int il = 0; il < 4; ++il) {
        int l = wid * 4 + il;
        const float* hr = hin + ((size_t)(b * LQ + l0 + l)) * DM;
        float v0 = hr[lane], v1 = hr[lane + 32];
        float ss = v0 * v0 + v1 * v1;
        #pragma unroll
        for (int s = 16; s; s >>= 1) ss += __shfl_xor_sync(~0u, ss, s);
        float r = rsqrtf(ss * (1.0f / DM) + EPSQ);
        s_nrow[l * 68 + lane]      = v0 * r * nw[lane];
        s_nrow[l * 68 + lane + 32] = v1 * r * nw[lane + 32];
    }
    __syncthreads();

    int c = tid;
    float acc[32];
    #pragma unroll
    for (int l = 0; l < 32; ++l) acc[l] = 0.f;

    #pragma unroll 1
    for (int k4 = 0; k4 < 16; ++k4) {
        float w0 = s_w[(k4 * 4 + 0) * 257 + c];
        float w1 = s_w[(k4 * 4 + 1) * 257 + c];
        float w2 = s_w[(k4 * 4 + 2) * 257 + c];
        float w3 = s_w[(k4 * 4 + 3) * 257 + c];
        #pragma unroll
        for (int l = 0; l < 32; ++l) {
            float4 x = *(const float4*)&s_nrow[l * 68 + k4 * 4];
            acc[l] += w0 * x.x + w1 * x.y + w2 * x.z + w3 * x.w;
        }
    }
    float bb = inb[c];
    float* xzp = g_xz + ((size_t)(b * LQ + l0)) * 256 + c;
    #pragma unroll
    for (int l = 0; l < 32; ++l) xzp[(size_t)l * 256] = acc[l] + bb;
}

// ================= K2: dwconv + silu + xproj + dtproj + softplus + packing =================
#define K2_SMEM_FLOATS 19264
#define K2_SMEM_BYTES  (K2_SMEM_FLOATS * 4)

__global__ void __launch_bounds__(256) k2_conv_xproj(
    const float* __restrict__ convw,
    const float* __restrict__ convb,
    const float* __restrict__ xprojw,
    const float* __restrict__ dtw,
    const float* __restrict__ dtb,
    const float* __restrict__ Dpw)
{
    extern __shared__ float sm[];
    float* s_xin   = sm;
    float* s_convw = sm + 47 * 128;
    float* s_xw    = sm;
    float* s_dbc   = sm + 68 * 128;
    float* s_xc    = sm + 10912;
    float* s_z     = sm + 15136;

    int b  = blockIdx.x >> 6;
    int l0 = (blockIdx.x & 63) << 5;
    int tid = threadIdx.x;

    for (int i = tid; i < 128 * 16; i += 256) s_convw[i] = convw[i];
    for (int i = tid; i < 47 * 128; i += 256) {
        int r = i >> 7, ch = i & 127;
        int l = l0 - 15 + r;
        s_xin[i] = (l >= 0) ? g_xz[((size_t)(b * LQ + l)) * 256 + ch] : 0.f;
    }
    for (int i = tid; i < 32 * 128; i += 256) {
        int l = i >> 7, ch = i & 127;
        s_z[l * 129 + ch] = g_xz[((size_t)(b * LQ + l0 + l)) * 256 + 128 + ch];
    }
    __syncthreads();

    for (int i = tid; i < 32 * 128; i += 256) {
        int l = i >> 7, ch = i & 127;
        float acc = convb[ch];
        #pragma unroll
        for (int j = 0; j < DCV; ++j)
            acc += s_convw[ch * DCV + j] * s_xin[(l + j) * 128 + ch];
        float sg = 1.f / (1.f + __expf(-acc));
        s_xc[l * 132 + ch] = acc * sg;
    }
    __syncthreads();

    for (int i = tid; i < 68 * 128; i += 256) s_xw[i] = xprojw[i];
    __syncthreads();

    {
        int l = tid & 31, rg = tid >> 5;
        if (rg * 9 < RQ) {
            float acc[9];
            #pragma unroll
            for (int r = 0; r < 9; ++r) acc[r] = 0.f;
            const float4* xc4 = (const float4*)(s_xc + l * 132);
            #pragma unroll 1
            for (int kc = 0; kc < 4; ++kc) {
                float4 xr[8];
                #pragma unroll
                for (int q = 0; q < 8; ++q) xr[q] = xc4[kc * 8 + q];
                #pragma unroll
                for (int rr = 0; rr < 9; ++rr) {
                    int r = rg * 9 + rr;
                    if (r < RQ) {
                        const float4* w4 = (const float4*)(s_xw + r * 128 + kc * 32);
                        float a = acc[rr];
                        #pragma unroll
                        for (int q = 0; q < 8; ++q) {
                            float4 w = w4[q];
                            a += w.x * xr[q].x + w.y * xr[q].y + w.z * xr[q].z + w.w * xr[q].w;
                        }
                        acc[rr] = a;
                    }
                }
            }
            #pragma unroll
            for (int rr = 0; rr < 9; ++rr) {
                int r = rg * 9 + rr;
                if (r < RQ) s_dbc[l * 69 + r] = acc[rr];
            }
        }
    }
    __syncthreads();

    for (int i = tid; i < 32 * 128; i += 256) {
        int e = i >> 5, l = i & 31;
        const float* dr = s_dbc + l * 69;
        float4 wv = __ldg((const float4*)(dtw + e * 4));
        float v = dr[0] * wv.x + dr[1] * wv.y + dr[2] * wv.z + dr[3] * wv.w + dtb[e];
        float delta = (v > 20.f) ? v : log1pf(__expf(v));
        float xcv = s_xc[l * 132 + e];
        float z  = s_z[l * 129 + e];
        float gz = z / (1.f + __expf(-z));
        size_t oidx = ((size_t)(b * ED + e)) * LQ + l0 + l;
        g_dx2[oidx]   = make_float2(delta, delta * xcv);
        g_gate2[oidx] = make_float2(gz, Dpw[e] * xcv * gz);
    }
    // pack B (bf16) and {B,C} (bf16x2) transposed per chunk: (b, chunk, n, t)
    {
        int chunk = l0 >> 8;       // CH = 256
        int tin   = l0 & (CH - 1);
        for (int i = tid; i < 32 * 32; i += 256) {
            int n = i >> 5, l = i & 31;
            const float* dr = s_dbc + l * 69;
            unsigned ub = __bfloat16_as_ushort(__float2bfloat16(dr[DTR + n]));
            unsigned uc = __bfloat16_as_ushort(__float2bfloat16(dr[DTR + NQ + n]));
            size_t base = (((size_t)(b * NCH + chunk)) * NQ + n) * CH + tin + l;
            g_bBT[base]  = __ushort_as_bfloat16((unsigned short)ub);
            g_bcTp[base] = (uc << 16) | ub;
        }
    }
}

// ================= K3a: local chunk scan (carry out) =================
// grid: eg(8) x chunk(8) x b(4) = 256 blocks; 512 threads = 16 warps = 16 e's.
// smem: s_b bf16 [NQ][CH+4] (16.6KB) + s_dx [EG][CH] float2 (32KB)
#define K3A_SMEM_BYTES (NQ * (CH + 4) * 2 + EG * CH * 8)

__global__ void __launch_bounds__(512) k3a_scan_local(const float* __restrict__ Alog)
{
    extern __shared__ char sma_raw[];
    __nv_bfloat16* s_b = (__nv_bfloat16*)sma_raw;               // [n][CH+4]
    float2 (*s_dx)[CH] = (float2(*)[CH])(sma_raw + NQ * (CH + 4) * 2);

    int eg = blockIdx.x & 7;
    int c  = (blockIdx.x >> 3) & 7;
    int b  = blockIdx.x >> 6;
    int tid = threadIdx.x, lane = tid & 31, w = tid >> 5;
    int e = eg * EG + w;

    {
        const uint2* src = (const uint2*)(g_bBT + (((size_t)(b * NCH + c)) * NQ) * CH);
        for (int i = tid; i < NQ * CH / 4; i += 512) {
            int n = i >> 6, q = i & 63;               // 64 uint2 (4 bf16) per n-row
            *(uint2*)(s_b + n * (CH + 4) + q * 4) = __ldg(src + i);
        }
        const float4* dsrc = (const float4*)(g_dx2 + ((size_t)(b * ED + e)) * LQ + c * CH);
        #pragma unroll
        for (int k = 0; k < CH / 64; ++k)
            *(float4*)(&s_dx[w][(k * 32 + lane) * 2]) = __ldg(dsrc + k * 32 + lane);
    }
    __syncthreads();

    float aA = -__expf(Alog[e * NQ + lane]) * LOG2EF;
    const __nv_bfloat16* bp = s_b + lane * (CH + 4);

    float h = 0.f, P = 1.f;
    #pragma unroll 4
    for (int j = 0; j < CH; j += 4) {
        uint2 u = *(const uint2*)(bp + j);             // 4 bf16 B's (this lane)
        float4 d0 = *(const float4*)(&s_dx[w][j]);     // steps j, j+1 (broadcast)
        float4 d1 = *(const float4*)(&s_dx[w][j + 2]); // steps j+2, j+3
        float B0 = __uint_as_float(u.x << 16);
        float B1 = __uint_as_float(u.x & 0xFFFF0000u);
        float B2 = __uint_as_float(u.y << 16);
        float B3 = __uint_as_float(u.y & 0xFFFF0000u);
        float dA;
        dA = ex2(d0.x * aA); h = fmaf(dA, h, d0.y * B0); P *= dA;
        dA = ex2(d0.z * aA); h = fmaf(dA, h, d0.w * B1); P *= dA;
        dA = ex2(d1.x * aA); h = fmaf(dA, h, d1.y * B2); P *= dA;
        dA = ex2(d1.z * aA); h = fmaf(dA, h, d1.w * B3); P *= dA;
    }
    g_carry[(((size_t)(b * ED + e)) * NCH + c) * NQ + lane] = make_float2(h, P);
}

// ================= K3c: combine prologue + rescan + multi-reduce (raw y out) =================
// smem: s_bc uint [NQ][CH+2] (33KB) + s_dx [EG][CH] float2 (32KB)
#define K3C_SMEM_BYTES (NQ * (CH + 2) * 4 + EG * CH * 8)

__global__ void __launch_bounds__(512) k3c_scan_out(const float* __restrict__ Alog)
{
    extern __shared__ char smc_raw[];
    unsigned* s_bc = (unsigned*)smc_raw;                        // [n][CH+2] packed bf16x2
    float2 (*s_dx)[CH] = (float2(*)[CH])(smc_raw + NQ * (CH + 2) * 4);

    int eg = blockIdx.x & 7;
    int c  = (blockIdx.x >> 3) & 7;
    int b  = blockIdx.x >> 6;
    int tid = threadIdx.x, lane = tid & 31, w = tid >> 5;
    int e = eg * EG + w;

    {
        const uint2* src = (const uint2*)(g_bcTp + (((size_t)(b * NCH + c)) * NQ) * CH);
        for (int i = tid; i < NQ * CH / 2; i += 512) {
            int n = i >> 7, q = i & 127;              // 128 uint2 per n-row
            *(uint2*)(s_bc + n * (CH + 2) + q * 2) = __ldg(src + i);
        }
        const float4* dsrc = (const float4*)(g_dx2 + ((size_t)(b * ED + e)) * LQ + c * CH);
        #pragma unroll
        for (int k = 0; k < CH / 64; ++k)
            *(float4*)(&s_dx[w][(k * 32 + lane) * 2]) = __ldg(dsrc + k * 32 + lane);
    }

    // prologue: exclusive combine of carries for chunks < c
    float h = 0.f;
    if (c > 0) {
        const float2* cp = g_carry + (((size_t)(b * ED + e)) * NCH) * NQ + lane;
        #pragma unroll
        for (int cc = 0; cc < NCH - 1; ++cc) {
            if (cc >= c) break;
            float2 v = __ldg(cp + (size_t)cc * NQ);
            h = fmaf(v.y, h, v.x);
        }
    }
    __syncthreads();

    float aA = -__expf(Alog[e * NQ + lane]) * LOG2EF;
    float* yp = g_yout + ((size_t)(b * ED + e)) * LQ + c * CH;
    const unsigned* bcl = s_bc + lane * (CH + 2);

    #pragma unroll 1
    for (int t0 = 0; t0 < CH; t0 += 32) {
        float v[32];
        #pragma unroll
        for (int j = 0; j < 32; j += 2) {
            uint2 u = *(const uint2*)(bcl + t0 + j);          // {B,C} bf16x2, steps j, j+1
            float4 dd = *(const float4*)(&s_dx[w][t0 + j]);   // dx steps j, j+1 (broadcast)
            float B0 = __uint_as_float(u.x << 16);
            float C0 = __uint_as_float(u.x & 0xFFFF0000u);
            float B1 = __uint_as_float(u.y << 16);
            float C1 = __uint_as_float(u.y & 0xFFFF0000u);
            float dA0 = ex2(dd.x * aA);
            h = fmaf(dA0, h, dd.y * B0);
            v[j] = h * C0;
            float dA1 = ex2(dd.z * aA);
            h = fmaf(dA1, h, dd.w * B1);
            v[j + 1] = h * C1;
        }
        // butterfly-transpose multi-reduce: lane L ends with sum for step t0+L
        #pragma unroll
        for (int d = 16; d >= 1; d >>= 1) {
            #pragma unroll
            for (int j = 0; j < d; ++j) {
                float send  = (lane & d) ? v[j] : v[j + d];
                float other = __shfl_xor_sync(~0u, send, d);
                float keep  = (lane & d) ? v[j + d] : v[j];
                v[j] = keep + other;
            }
        }
        yp[t0 + lane] = v[0];                                 // raw y; gate applied downstream
    }
}

// ================= K4: gate + out_proj + residual =================
#define K4_SMEM_FLOATS (128 * 65 + 128 * 36)
#define K4_SMEM_BYTES  (K4_SMEM_FLOATS * 4)

__global__ void __launch_bounds__(256) k4_outproj(
    const float* __restrict__ ow,   // (64, 128)
    const float* __restrict__ ob,
    const float* __restrict__ hin,
    float* __restrict__ hout)
{
    extern __shared__ float sm4[];
    float* s_wT = sm4;               // [k=128][d=64] pad 65
    float* s_yT = sm4 + 128 * 65;    // [k=128][l=32] pad 36

    int b  = blockIdx.x >> 6;
    int l0 = (blockIdx.x & 63) << 5;
    int tid = threadIdx.x;

    for (int i = tid; i < 64 * 128; i += 256)
        s_wT[(i & 127) * 65 + (i >> 7)] = ow[i];
    for (int i = tid; i < 128 * 32; i += 256) {
        int e = i >> 5, l = i & 31;
        size_t idx = ((size_t)(b * ED + e)) * LQ + l0 + l;
        float yr = g_yout[idx];
        float2 g = __ldg(&g_gate2[idx]);
        s_yT[e * 36 + l] = fmaf(yr, g.x, g.y);               // apply gate here
    }
    __syncthreads();

    int d = tid & 63, lg = tid >> 6;
    float acc[8];
    #pragma unroll
    for (int j = 0; j < 8; ++j) acc[j] = 0.f;

    #pragma unroll 4
    for (int k = 0; k < 128; ++k) {
        float w = s_wT[k * 65 + d];
        float4 x0 = *(const float4*)&s_yT[k * 36 + lg * 8];
        float4 x1 = *(const float4*)&s_yT[k * 36 + lg * 8 + 4];
        acc[0] += w * x0.x; acc[1] += w * x0.y; acc[2] += w * x0.z; acc[3] += w * x0.w;
        acc[4] += w * x1.x; acc[5] += w * x1.y; acc[6] += w * x1.z; acc[7] += w * x1.w;
    }

    float bias = ob[d];
    #pragma unroll
    for (int j = 0; j < 8; ++j) {
        int l = lg * 8 + j;
        size_t idx = ((size_t)(b * LQ + l0 + l)) * DM + d;
        hout[idx] = hin[idx] + bias + acc[j];
    }
}

// ================= final classifier head (applies gate to last step) =================
__global__ void __launch_bounds__(128) k_final(
    const float* __restrict__ fcw, const float* __restrict__ fcb, float* __restrict__ out)
{
    int b = threadIdx.x >> 5, lane = threadIdx.x & 31;
    float s = 0.f;
    #pragma unroll
    for (int j = 0; j < 4; ++j) {
        int e = lane + 32 * j;
        size_t idx = ((size_t)(b * 128 + e)) * LQ + (LQ - 1);
        float yr = g_yout[idx];
        float2 g = g_gate2[idx];
        s += fmaf(yr, g.x, g.y) * fcw[e];
    }
    #pragma unroll
    for (int d = 16; d; d >>= 1) s += __shfl_xor_sync(~0u, s, d);
    if (lane == 0) out[b] = s + fcb[0];
}

// ================= launch =================
extern "C" void kernel_launch(void* const* d_in, const int* in_sizes, int n_in,
                              void* d_out, int out_size)
{
    const float* x        = (const float*)d_in[0];
    const float* in_w     = (const float*)d_in[1];
    const float* in_b     = (const float*)d_in[2];
    const float* conv_w   = (const float*)d_in[3];
    const float* conv_b   = (const float*)d_in[4];
    const float* xproj_w  = (const float*)d_in[5];
    const float* dtproj_w = (const float*)d_in[6];
    const float* dtproj_b = (const float*)d_in[7];
    const float* A_log    = (const float*)d_in[8];
    const float* Dp       = (const float*)d_in[9];
    const float* outp_w   = (const float*)d_in[10];
    const float* outp_b   = (const float*)d_in[11];
    const float* norm_w   = (const float*)d_in[12];
    const float* fc_w     = (const float*)d_in[13];
    const float* fc_b     = (const float*)d_in[14];
    float* out = (float*)d_out;

    (void)in_sizes; (void)n_in; (void)out_size;

    cudaFuncSetAttribute(k1_rms_inproj,  cudaFuncAttributeMaxDynamicSharedMemorySize, K1_SMEM_BYTES);
    cudaFuncSetAttribute(k2_conv_xproj,  cudaFuncAttributeMaxDynamicSharedMemorySize, K2_SMEM_BYTES);
    cudaFuncSetAttribute(k3a_scan_local, cudaFuncAttributeMaxDynamicSharedMemorySize, K3A_SMEM_BYTES);
    cudaFuncSetAttribute(k3c_scan_out,   cudaFuncAttributeMaxDynamicSharedMemorySize, K3C_SMEM_BYTES);
    cudaFuncSetAttribute(k4_outproj,     cudaFuncAttributeMaxDynamicSharedMemorySize, K4_SMEM_BYTES);

    float* gh = nullptr;
    cudaGetSymbolAddress((void**)&gh, g_h);

    for (int i = 0; i < 4; ++i) {
        const float* hin = (i == 0) ? x : gh;
        k1_rms_inproj<<<256, 256, K1_SMEM_BYTES>>>(hin,
                                    in_w + (size_t)i * 2 * ED * DM,
                                    in_b + (size_t)i * 2 * ED,
                                    norm_w + (size_t)i * DM);
        k2_conv_xproj<<<256, 256, K2_SMEM_BYTES>>>(
            conv_w   + (size_t)i * ED * DCV,
            conv_b   + (size_t)i * ED,
            xproj_w  + (size_t)i * RQ * ED,
            dtproj_w + (size_t)i * ED * DTR,
            dtproj_b + (size_t)i * ED,
            Dp       + (size_t)i * ED);
        const float* Al = A_log + (size_t)i * ED * NQ;
        k3a_scan_local<<<256, 512, K3A_SMEM_BYTES>>>(Al);
        k3c_scan_out<<<256, 512, K3C_SMEM_BYTES>>>(Al);
        if (i < 3)
            k4_outproj<<<256, 256, K4_SMEM_BYTES>>>(
                outp_w + (size_t)i * DM * ED,
                outp_b + (size_t)i * DM,
                hin, gh);
    }
    k_final<<<1, 128>>>(fc_w, fc_b, out);
}

// round 10
// speedup vs baseline: 1.7406x; 1.0243x over previous
#include <cuda_runtime.h>
#include <cuda_fp16.h>

#define BQ 4
#define LQ 2048
#define DM 64
#define ED 128
#define NQ 32
#define DCV 16
#define DTR 4
#define RQ 68            // DTR + 2*N
#define EPSQ 1e-5f
#define LOG2EF 1.4426950408889634f

#define CH 256           // steps per chunk (k3)
#define NCH 8            // chunks
#define EG 16            // e-channels per scan block

// ---------------- scratch (device globals; no allocation allowed) ----------------
__device__ float  g_h[BQ * LQ * DM];               // residual stream
__device__ float  g_xz[BQ * LQ * 2 * ED];          // in_proj output (b,l,2e)
__device__ float2 g_dx2[BQ * ED * LQ];             // {delta, delta*xc}  (b,e,l)
__device__ float2 g_gate2[BQ * ED * LQ];           // {silu(z), Dp*xc*silu(z)} (b,e,l)
__device__ __half g_bBT[BQ * NCH * NQ * CH];       // B fp16, (b,chunk,n,t)
__device__ unsigned g_bcTp[BQ * NCH * NQ * CH];    // {B lo, C hi} fp16x2, (b,chunk,n,t)
__device__ float  g_yout[BQ * ED * LQ];            // RAW scan output (b,e,l)
__device__ float2 g_carry[BQ * ED * NCH * NQ];     // {h_final, P}

__device__ __forceinline__ float ex2(float x) {
    float r; asm("ex2.approx.ftz.f32 %0, %1;" : "=f"(r) : "f"(x)); return r;
}

// ================= K1: rmsnorm + in_proj (layer 0 only) =================
#define K1_SMEM_FLOATS (64 * 257 + 32 * 68)
#define K1_SMEM_BYTES  (K1_SMEM_FLOATS * 4)

__global__ void __launch_bounds__(256) k1_rms_inproj(
    const float* __restrict__ hin,
    const float* __restrict__ inw,   // (256, 64)
    const float* __restrict__ inb,
    const float* __restrict__ nw)
{
    extern __shared__ float sm1[];
    float* s_w    = sm1;              // [k=64][c=256] pad 257
    float* s_nrow = sm1 + 64 * 257;   // [l=32][k=64] pad 68

    int b  = blockIdx.x >> 6;
    int l0 = (blockIdx.x & 63) << 5;
    int tid = threadIdx.x;
    int lane = tid & 31, wid = tid >> 5;

    for (int i = tid; i < 256 * 64; i += 256)
        s_w[(i & 63) * 257 + (i >> 6)] = inw[i];

    #pragma unroll
    for (int il = 0; il < 4; ++il) {
        int l = wid * 4 + il;
        const float* hr = hin + ((size_t)(b * LQ + l0 + l)) * DM;
        float v0 = hr[lane], v1 = hr[lane + 32];
        float ss = v0 * v0 + v1 * v1;
        #pragma unroll
        for (int s = 16; s; s >>= 1) ss += __shfl_xor_sync(~0u, ss, s);
        float r = rsqrtf(ss * (1.0f / DM) + EPSQ);
        s_nrow[l * 68 + lane]      = v0 * r * nw[lane];
        s_nrow[l * 68 + lane + 32] = v1 * r * nw[lane + 32];
    }
    __syncthreads();

    int c = tid;
    float acc[32];
    #pragma unroll
    for (int l = 0; l < 32; ++l) acc[l] = 0.f;

    #pragma unroll 1
    for (int k4 = 0; k4 < 16; ++k4) {
        float w0 = s_w[(k4 * 4 + 0) * 257 + c];
        float w1 = s_w[(k4 * 4 + 1) * 257 + c];
        float w2 = s_w[(k4 * 4 + 2) * 257 + c];
        float w3 = s_w[(k4 * 4 + 3) * 257 + c];
        #pragma unroll
        for (int l = 0; l < 32; ++l) {
            float4 x = *(const float4*)&s_nrow[l * 68 + k4 * 4];
            acc[l] += w0 * x.x + w1 * x.y + w2 * x.z + w3 * x.w;
        }
    }
    float bb = inb[c];
    float* xzp = g_xz + ((size_t)(b * LQ + l0)) * 256 + c;
    #pragma unroll
    for (int l = 0; l < 32; ++l) xzp[(size_t)l * 256] = acc[l] + bb;
}

// ================= K41: gate + out_proj + residual + rmsnorm + in_proj (fused) =================
// phase A smem: s_wT[128*65]@0, s_yT[128*36]@8320   (ends 12928)
// phase B smem: s_w[64*257]@0,  s_nrow[32*68]@16448 (ends 18624) — s_nrow beyond phase A
#define K41_SMEM_FLOATS 18624
#define K41_SMEM_BYTES  (K41_SMEM_FLOATS * 4)

__global__ void __launch_bounds__(256) k41_out_rms_in(
    const float* __restrict__ ow,    // (64, 128)  layer i-1
    const float* __restrict__ ob,
    const float* __restrict__ hin,   // residual input of layer i-1
    float* __restrict__ hout,        // g_h
    const float* __restrict__ inw,   // (256, 64)  layer i
    const float* __restrict__ inb,
    const float* __restrict__ nw)
{
    extern __shared__ float smf[];
    float* s_wT   = smf;              // [k=128][d=64] pad 65
    float* s_yT   = smf + 128 * 65;   // [e=128][l=32] pad 36
    float* s_w    = smf;              // phase B: [k=64][c=256] pad 257
    float* s_nrow = smf + 16448;      // [l=32][k=64] pad 68

    int b  = blockIdx.x >> 6;
    int l0 = (blockIdx.x & 63) << 5;
    int tid = threadIdx.x;
    int lane = tid & 31, wid = tid >> 5;

    // ---- phase A: stage out_proj weights + gated y ----
    for (int i = tid; i < 64 * 128; i += 256)
        s_wT[(i & 127) * 65 + (i >> 7)] = ow[i];
    for (int i = tid; i < 128 * 32; i += 256) {
        int e = i >> 5, l = i & 31;
        size_t idx = ((size_t)(b * ED + e)) * LQ + l0 + l;
        float yr = g_yout[idx];
        float2 g = __ldg(&g_gate2[idx]);
        s_yT[e * 36 + l] = fmaf(yr, g.x, g.y);
    }
    __syncthreads();

    int d = tid & 63, lg = tid >> 6;
    float acc[8];
    #pragma unroll
    for (int j = 0; j < 8; ++j) acc[j] = 0.f;

    #pragma unroll 4
    for (int k = 0; k < 128; ++k) {
        float w = s_wT[k * 65 + d];
        float4 x0 = *(const float4*)&s_yT[k * 36 + lg * 8];
        float4 x1 = *(const float4*)&s_yT[k * 36 + lg * 8 + 4];
        acc[0] += w * x0.x; acc[1] += w * x0.y; acc[2] += w * x0.z; acc[3] += w * x0.w;
        acc[4] += w * x1.x; acc[5] += w * x1.y; acc[6] += w * x1.z; acc[7] += w * x1.w;
    }

    float bias = ob[d];
    #pragma unroll
    for (int j = 0; j < 8; ++j) {
        int l = lg * 8 + j;
        size_t idx = ((size_t)(b * LQ + l0 + l)) * DM + d;
        float hv = hin[idx] + bias + acc[j];
        hout[idx] = hv;
        s_nrow[l * 68 + d] = hv;      // region disjoint from phase A smem
    }
    __syncthreads();                   // phase A reads done; h rows complete

    // ---- phase B: stage in_proj weights (aliases phase A region) ----
    for (int i = tid; i < 256 * 64; i += 256)
        s_w[(i & 63) * 257 + (i >> 6)] = inw[i];

    // rmsnorm rows in place (each row owned by one warp)
    #pragma unroll
    for (int il = 0; il < 4; ++il) {
        int l = wid * 4 + il;
        float v0 = s_nrow[l * 68 + lane], v1 = s_nrow[l * 68 + lane + 32];
        float ss = v0 * v0 + v1 * v1;
        #pragma unroll
        for (int s = 16; s; s >>= 1) ss += __shfl_xor_sync(~0u, ss, s);
        float r = rsqrtf(ss * (1.0f / DM) + EPSQ);
        s_nrow[l * 68 + lane]      = v0 * r * nw[lane];
        s_nrow[l * 68 + lane + 32] = v1 * r * nw[lane + 32];
    }
    __syncthreads();

    // in_proj GEMM
    int c = tid;
    float a2[32];
    #pragma unroll
    for (int l = 0; l < 32; ++l) a2[l] = 0.f;

    #pragma unroll 1
    for (int k4 = 0; k4 < 16; ++k4) {
        float w0 = s_w[(k4 * 4 + 0) * 257 + c];
        float w1 = s_w[(k4 * 4 + 1) * 257 + c];
        float w2 = s_w[(k4 * 4 + 2) * 257 + c];
        float w3 = s_w[(k4 * 4 + 3) * 257 + c];
        #pragma unroll
        for (int l = 0; l < 32; ++l) {
            float4 x = *(const float4*)&s_nrow[l * 68 + k4 * 4];
            a2[l] += w0 * x.x + w1 * x.y + w2 * x.z + w3 * x.w;
        }
    }
    float bb = inb[c];
    float* xzp = g_xz + ((size_t)(b * LQ + l0)) * 256 + c;
    #pragma unroll
    for (int l = 0; l < 32; ++l) xzp[(size_t)l * 256] = a2[l] + bb;
}

// ================= K2: dwconv + silu + xproj + dtproj + softplus + packing =================
#define K2_SMEM_FLOATS 19264
#define K2_SMEM_BYTES  (K2_SMEM_FLOATS * 4)

__global__ void __launch_bounds__(256) k2_conv_xproj(
    const float* __restrict__ convw,
    const float* __restrict__ convb,
    const float* __restrict__ xprojw,
    const float* __restrict__ dtw,
    const float* __restrict__ dtb,
    const float* __restrict__ Dpw)
{
    extern __shared__ float sm[];
    float* s_xin   = sm;
    float* s_convw = sm + 47 * 128;
    float* s_xw    = sm;
    float* s_dbc   = sm + 68 * 128;
    float* s_xc    = sm + 10912;
    float* s_z     = sm + 15136;

    int b  = blockIdx.x >> 6;
    int l0 = (blockIdx.x & 63) << 5;
    int tid = threadIdx.x;

    for (int i = tid; i < 128 * 16; i += 256) s_convw[i] = convw[i];
    for (int i = tid; i < 47 * 128; i += 256) {
        int r = i >> 7, ch = i & 127;
        int l = l0 - 15 + r;
        s_xin[i] = (l >= 0) ? g_xz[((size_t)(b * LQ + l)) * 256 + ch] : 0.f;
    }
    for (int i = tid; i < 32 * 128; i += 256) {
        int l = i >> 7, ch = i & 127;
        s_z[l * 129 + ch] = g_xz[((size_t)(b * LQ + l0 + l)) * 256 + 128 + ch];
    }
    __syncthreads();

    for (int i = tid; i < 32 * 128; i += 256) {
        int l = i >> 7, ch = i & 127;
        float acc = convb[ch];
        #pragma unroll
        for (int j = 0; j < DCV; ++j)
            acc += s_convw[ch * DCV + j] * s_xin[(l + j) * 128 + ch];
        float sg = 1.f / (1.f + __expf(-acc));
        s_xc[l * 132 + ch] = acc * sg;
    }
    __syncthreads();

    for (int i = tid; i < 68 * 128; i += 256) s_xw[i] = xprojw[i];
    __syncthreads();

    {
        int l = tid & 31, rg = tid >> 5;
        if (rg * 9 < RQ) {
            float acc[9];
            #pragma unroll
            for (int r = 0; r < 9; ++r) acc[r] = 0.f;
            const float4* xc4 = (const float4*)(s_xc + l * 132);
            #pragma unroll 1
            for (int kc = 0; kc < 4; ++kc) {
                float4 xr[8];
                #pragma unroll
                for (int q = 0; q < 8; ++q) xr[q] = xc4[kc * 8 + q];
                #pragma unroll
                for (int rr = 0; rr < 9; ++rr) {
                    int r = rg * 9 + rr;
                    if (r < RQ) {
                        const float4* w4 = (const float4*)(s_xw + r * 128 + kc * 32);
                        float a = acc[rr];
                        #pragma unroll
                        for (int q = 0; q < 8; ++q) {
                            float4 w = w4[q];
                            a += w.x * xr[q].x + w.y * xr[q].y + w.z * xr[q].z + w.w * xr[q].w;
                        }
                        acc[rr] = a;
                    }
                }
            }
            #pragma unroll
            for (int rr = 0; rr < 9; ++rr) {
                int r = rg * 9 + rr;
                if (r < RQ) s_dbc[l * 69 + r] = acc[rr];
            }
        }
    }
    __syncthreads();

    for (int i = tid; i < 32 * 128; i += 256) {
        int e = i >> 5, l = i & 31;
        const float* dr = s_dbc + l * 69;
        float4 wv = __ldg((const float4*)(dtw + e * 4));
        float v = dr[0] * wv.x + dr[1] * wv.y + dr[2] * wv.z + dr[3] * wv.w + dtb[e];
        float delta = (v > 20.f) ? v : log1pf(__expf(v));
        float xcv = s_xc[l * 132 + e];
        float z  = s_z[l * 129 + e];
        float gz = z / (1.f + __expf(-z));
        size_t oidx = ((size_t)(b * ED + e)) * LQ + l0 + l;
        g_dx2[oidx]   = make_float2(delta, delta * xcv);
        g_gate2[oidx] = make_float2(gz, Dpw[e] * xcv * gz);
    }
    // pack B (fp16) and {B,C} (fp16x2) transposed per chunk: (b, chunk, n, t)
    {
        int chunk = l0 >> 8;       // CH = 256
        int tin   = l0 & (CH - 1);
        for (int i = tid; i < 32 * 32; i += 256) {
            int n = i >> 5, l = i & 31;
            const float* dr = s_dbc + l * 69;
            float Bv = dr[DTR + n], Cv = dr[DTR + NQ + n];
            __half2 bc = __floats2half2_rn(Bv, Cv);   // lo = B, hi = C
            size_t base = (((size_t)(b * NCH + chunk)) * NQ + n) * CH + tin + l;
            g_bBT[base]  = __low2half(bc);
            g_bcTp[base] = *(unsigned*)&bc;
        }
    }
}

// ================= K3a: local chunk scan (carry out) =================
// smem: s_b fp16 [NQ][CH+4] (16.6KB) + s_dx [EG][CH] float2 (32KB)
#define K3A_SMEM_BYTES (NQ * (CH + 4) * 2 + EG * CH * 8)

__global__ void __launch_bounds__(512) k3a_scan_local(const float* __restrict__ Alog)
{
    extern __shared__ char sma_raw[];
    __half* s_b = (__half*)sma_raw;                             // [n][CH+4]
    float2 (*s_dx)[CH] = (float2(*)[CH])(sma_raw + NQ * (CH + 4) * 2);

    int eg = blockIdx.x & 7;
    int c  = (blockIdx.x >> 3) & 7;
    int b  = blockIdx.x >> 6;
    int tid = threadIdx.x, lane = tid & 31, w = tid >> 5;
    int e = eg * EG + w;

    {
        const uint2* src = (const uint2*)(g_bBT + (((size_t)(b * NCH + c)) * NQ) * CH);
        for (int i = tid; i < NQ * CH / 4; i += 512) {
            int n = i >> 6, q = i & 63;
            *(uint2*)(s_b + n * (CH + 4) + q * 4) = __ldg(src + i);
        }
        const float4* dsrc = (const float4*)(g_dx2 + ((size_t)(b * ED + e)) * LQ + c * CH);
        #pragma unroll
        for (int k = 0; k < CH / 64; ++k)
            *(float4*)(&s_dx[w][(k * 32 + lane) * 2]) = __ldg(dsrc + k * 32 + lane);
    }
    __syncthreads();

    float aA = -__expf(Alog[e * NQ + lane]) * LOG2EF;
    const __half* bp = s_b + lane * (CH + 4);

    float h = 0.f, P = 1.f;
    #pragma unroll 4
    for (int j = 0; j < CH; j += 4) {
        uint2 u = *(const uint2*)(bp + j);             // 4 fp16 B's
        float4 d0 = *(const float4*)(&s_dx[w][j]);
        float4 d1 = *(const float4*)(&s_dx[w][j + 2]);
        float2 b01 = __half22float2(*(const __half2*)&u.x);
        float2 b23 = __half22float2(*(const __half2*)&u.y);
        float dA;
        dA = ex2(d0.x * aA); h = fmaf(dA, h, d0.y * b01.x); P *= dA;
        dA = ex2(d0.z * aA); h = fmaf(dA, h, d0.w * b01.y); P *= dA;
        dA = ex2(d1.x * aA); h = fmaf(dA, h, d1.y * b23.x); P *= dA;
        dA = ex2(d1.z * aA); h = fmaf(dA, h, d1.w * b23.y); P *= dA;
    }
    g_carry[(((size_t)(b * ED + e)) * NCH + c) * NQ + lane] = make_float2(h, P);
}

// ================= K3c: combine prologue + rescan + multi-reduce (raw y out) =================
// smem: s_bc uint [NQ][CH+2] (33KB) + s_dx [EG][CH] float2 (32KB)
#define K3C_SMEM_BYTES (NQ * (CH + 2) * 4 + EG * CH * 8)

__global__ void __launch_bounds__(512) k3c_scan_out(const float* __restrict__ Alog)
{
    extern __shared__ char smc_raw[];
    unsigned* s_bc = (unsigned*)smc_raw;                        // [n][CH+2] packed fp16x2
    float2 (*s_dx)[CH] = (float2(*)[CH])(smc_raw + NQ * (CH + 2) * 4);

    int eg = blockIdx.x & 7;
    int c  = (blockIdx.x >> 3) & 7;
    int b  = blockIdx.x >> 6;
    int tid = threadIdx.x, lane = tid & 31, w = tid >> 5;
    int e = eg * EG + w;

    {
        const uint2* src = (const uint2*)(g_bcTp + (((size_t)(b * NCH + c)) * NQ) * CH);
        for (int i = tid; i < NQ * CH / 2; i += 512) {
            int n = i >> 7, q = i & 127;
            *(uint2*)(s_bc + n * (CH + 2) + q * 2) = __ldg(src + i);
        }
        const float4* dsrc = (const float4*)(g_dx2 + ((size_t)(b * ED + e)) * LQ + c * CH);
        #pragma unroll
        for (int k = 0; k < CH / 64; ++k)
            *(float4*)(&s_dx[w][(k * 32 + lane) * 2]) = __ldg(dsrc + k * 32 + lane);
    }

    float h = 0.f;
    if (c > 0) {
        const float2* cp = g_carry + (((size_t)(b * ED + e)) * NCH) * NQ + lane;
        #pragma unroll
        for (int cc = 0; cc < NCH - 1; ++cc) {
            if (cc >= c) break;
            float2 v = __ldg(cp + (size_t)cc * NQ);
            h = fmaf(v.y, h, v.x);
        }
    }
    __syncthreads();

    float aA = -__expf(Alog[e * NQ + lane]) * LOG2EF;
    float* yp = g_yout + ((size_t)(b * ED + e)) * LQ + c * CH;
    const unsigned* bcl = s_bc + lane * (CH + 2);

    #pragma unroll 1
    for (int t0 = 0; t0 < CH; t0 += 32) {
        float v[32];
        #pragma unroll
        for (int j = 0; j < 32; j += 2) {
            uint2 u = *(const uint2*)(bcl + t0 + j);          // {B,C} fp16x2, steps j, j+1
            float4 dd = *(const float4*)(&s_dx[w][t0 + j]);
            float2 bc0 = __half22float2(*(const __half2*)&u.x);
            float2 bc1 = __half22float2(*(const __half2*)&u.y);
            float dA0 = ex2(dd.x * aA);
            h = fmaf(dA0, h, dd.y * bc0.x);
            v[j] = h * bc0.y;
            float dA1 = ex2(dd.z * aA);
            h = fmaf(dA1, h, dd.w * bc1.x);
            v[j + 1] = h * bc1.y;
        }
        #pragma unroll
        for (int d = 16; d >= 1; d >>= 1) {
            #pragma unroll
            for (int j = 0; j < d; ++j) {
                float send  = (lane & d) ? v[j] : v[j + d];
                float other = __shfl_xor_sync(~0u, send, d);
                float keep  = (lane & d) ? v[j + d] : v[j];
                v[j] = keep + other;
            }
        }
        yp[t0 + lane] = v[0];
    }
}

// ================= final classifier head =================
__global__ void __launch_bounds__(128) k_final(
    const float* __restrict__ fcw, const float* __restrict__ fcb, float* __restrict__ out)
{
    int b = threadIdx.x >> 5, lane = threadIdx.x & 31;
    float s = 0.f;
    #pragma unroll
    for (int j = 0; j < 4; ++j) {
        int e = lane + 32 * j;
        size_t idx = ((size_t)(b * 128 + e)) * LQ + (LQ - 1);
        float yr = g_yout[idx];
        float2 g = g_gate2[idx];
        s += fmaf(yr, g.x, g.y) * fcw[e];
    }
    #pragma unroll
    for (int d = 16; d; d >>= 1) s += __shfl_xor_sync(~0u, s, d);
    if (lane == 0) out[b] = s + fcb[0];
}

// ================= launch =================
extern "C" void kernel_launch(void* const* d_in, const int* in_sizes, int n_in,
                              void* d_out, int out_size)
{
    const float* x        = (const float*)d_in[0];
    const float* in_w     = (const float*)d_in[1];
    const float* in_b     = (const float*)d_in[2];
    const float* conv_w   = (const float*)d_in[3];
    const float* conv_b   = (const float*)d_in[4];
    const float* xproj_w  = (const float*)d_in[5];
    const float* dtproj_w = (const float*)d_in[6];
    const float* dtproj_b = (const float*)d_in[7];
    const float* A_log    = (const float*)d_in[8];
    const float* Dp       = (const float*)d_in[9];
    const float* outp_w   = (const float*)d_in[10];
    const float* outp_b   = (const float*)d_in[11];
    const float* norm_w   = (const float*)d_in[12];
    const float* fc_w     = (const float*)d_in[13];
    const float* fc_b     = (const float*)d_in[14];
    float* out = (float*)d_out;

    (void)in_sizes; (void)n_in; (void)out_size;

    cudaFuncSetAttribute(k1_rms_inproj,  cudaFuncAttributeMaxDynamicSharedMemorySize, K1_SMEM_BYTES);
    cudaFuncSetAttribute(k41_out_rms_in, cudaFuncAttributeMaxDynamicSharedMemorySize, K41_SMEM_BYTES);
    cudaFuncSetAttribute(k2_conv_xproj,  cudaFuncAttributeMaxDynamicSharedMemorySize, K2_SMEM_BYTES);
    cudaFuncSetAttribute(k3a_scan_local, cudaFuncAttributeMaxDynamicSharedMemorySize, K3A_SMEM_BYTES);
    cudaFuncSetAttribute(k3c_scan_out,   cudaFuncAttributeMaxDynamicSharedMemorySize, K3C_SMEM_BYTES);

    float* gh = nullptr;
    cudaGetSymbolAddress((void**)&gh, g_h);

    for (int i = 0; i < 4; ++i) {
        if (i == 0) {
            k1_rms_inproj<<<256, 256, K1_SMEM_BYTES>>>(x,
                                        in_w + 0,
                                        in_b + 0,
                                        norm_w + 0);
        } else {
            const float* hin = (i == 1) ? x : gh;
            k41_out_rms_in<<<256, 256, K41_SMEM_BYTES>>>(
                outp_w + (size_t)(i - 1) * DM * ED,
                outp_b + (size_t)(i - 1) * DM,
                hin, gh,
                in_w + (size_t)i * 2 * ED * DM,
                in_b + (size_t)i * 2 * ED,
                norm_w + (size_t)i * DM);
        }
        k2_conv_xproj<<<256, 256, K2_SMEM_BYTES>>>(
            conv_w   + (size_t)i * ED * DCV,
            conv_b   + (size_t)i * ED,
            xproj_w  + (size_t)i * RQ * ED,
            dtproj_w + (size_t)i * ED * DTR,
            dtproj_b + (size_t)i * ED,
            Dp       + (size_t)i * ED);
        const float* Al = A_log + (size_t)i * ED * NQ;
        k3a_scan_local<<<256, 512, K3A_SMEM_BYTES>>>(Al);
        k3c_scan_out<<<256, 512, K3C_SMEM_BYTES>>>(Al);
    }
    k_final<<<1, 128>>>(fc_w, fc_b, out);
}